// round 6
// baseline (speedup 1.0000x reference)
#include <cuda_runtime.h>
#include <cuda_bf16.h>
#include <math.h>
#include <stdint.h>

// ---------------- problem constants ----------------
#define K_   256
#define KP1  257
#define D_   256
#define V_   50000
#define T_   512
#define B_   256
#define MD   512              // M*D
#define R2   66049            // KP1*KP1
#define EPS  1e-5f

#define NRT  517              // ceil(R2/128)
#define NVT  391              // ceil(V/128)

// ---------------- fp32 GEMM tiling (small kernels) ----------------
#define BM   64
#define BN   256
#define BKK  16
#define MI(i) (((i) < 4) ? (ty * 4 + (i)) : (32 + ty * 4 + ((i) - 4)))
#define NJ(j) (((j) < 4) ? (tx * 4 + (j)) : (128 + tx * 4 + ((j) - 4)))

// ---------------- scratch ----------------
__device__ float g_h[K_ * D_];
__device__ __nv_bfloat16 g_h_bf[K_ * D_];
__device__ float g_lse_em[K_];
__device__ float g_part_em[NVT * K_];
__device__ float g_At[KP1 * MD];
__device__ float g_Bt[KP1 * MD];
__device__ __nv_bfloat16 g_th_bf[(size_t)R2 * MD];   // 67.6 MB
__device__ __nv_bfloat16 g_tdW_bf[K_ * MD];
__device__ __nv_bfloat16 g_decW_bf[(size_t)V_ * D_]; // 25.6 MB
__device__ float g_lseT[R2];

// ================= mma.sync helpers =================
__device__ __forceinline__ uint32_t s2u(const void* p) {
    uint32_t a;
    asm("{ .reg .u64 t; cvta.to.shared.u64 t, %1; cvt.u32.u64 %0, t; }" : "=r"(a) : "l"(p));
    return a;
}
__device__ __forceinline__ uint32_t pack_bf2(float a, float b) {
    uint32_t u;
    asm("cvt.rn.bf16x2.f32 %0, %1, %2;" : "=r"(u) : "f"(b), "f"(a));
    return u;
}
__device__ __forceinline__ float dotu(uint32_t a, uint32_t b) {
    float2 fa = __bfloat1622float2(*reinterpret_cast<const __nv_bfloat162*>(&a));
    float2 fb = __bfloat1622float2(*reinterpret_cast<const __nv_bfloat162*>(&b));
    return fa.x * fb.x + fa.y * fb.y;
}
__device__ __forceinline__ void cp16(uint32_t dst, const void* src, bool ok) {
    int sz = ok ? 16 : 0;
    asm volatile("cp.async.cg.shared.global [%0], [%1], 16, %2;"
                 :: "r"(dst), "l"(src), "r"(sz) : "memory");
}
#define CP_COMMIT() asm volatile("cp.async.commit_group;" ::: "memory")
#define CP_WAIT(n)  asm volatile("cp.async.wait_group %0;" :: "n"(n) : "memory")

#define LDSM4(r, addr) \
    asm volatile("ldmatrix.sync.aligned.m8n8.x4.shared.b16 {%0,%1,%2,%3}, [%4];" \
                 : "=r"((r)[0]), "=r"((r)[1]), "=r"((r)[2]), "=r"((r)[3]) : "r"(addr))

#define MMA16816(c, a, b0v, b1v) \
    asm volatile("mma.sync.aligned.m16n8k16.row.col.f32.bf16.bf16.f32 " \
                 "{%0,%1,%2,%3}, {%4,%5,%6,%7}, {%8,%9}, {%0,%1,%2,%3};" \
                 : "+f"((c)[0]), "+f"((c)[1]), "+f"((c)[2]), "+f"((c)[3]) \
                 : "r"((a)[0]), "r"((a)[1]), "r"((a)[2]), "r"((a)[3]), "r"(b0v), "r"(b1v))

// smem stage layout: A 128 rows x 80B = 10240, B 256 rows x 80B = 20480
#define ASZ    10240
#define STAGE  30720
#define SMEMSZ (2 * STAGE)

// ---------------- HMMA pipeline core ----------------
// C[128 x 256] tile: A rows m0.., B all 256 rows; NC chunks of K=32.
// 512 threads, 16 warps: wm = wid&7 (16-row slice), wn = wid>>3 (128-col half).
__device__ __forceinline__ void mma_pipeline(
    const __nv_bfloat16* __restrict__ Aptr, int lda, int AM,
    const __nv_bfloat16* __restrict__ Bptr, int ldb,
    int NC, int m0, uint32_t sbase, float acc[16][4])
{
    const int tid = threadIdx.x;
    const int lane = tid & 31, wid = tid >> 5;
    const int wm = wid & 7, wn = wid >> 3;

    // global->smem load mapping: thread t loads A quad (row=t>>2, q=t&3) and two B quads
    const int arow = tid >> 2, aq = tid & 3;
    const int gmA = m0 + arow;
    const bool aok = gmA < AM;
    const __nv_bfloat16* asrc = Aptr + (size_t)(aok ? gmA : 0) * lda + aq * 8;
    const __nv_bfloat16* bsrc1 = Bptr + (size_t)arow * ldb + aq * 8;
    const __nv_bfloat16* bsrc2 = Bptr + (size_t)(128 + arow) * ldb + aq * 8;
    const uint32_t adst  = sbase + arow * 80 + aq * 16;
    const uint32_t bdst1 = sbase + ASZ + arow * 80 + aq * 16;
    const uint32_t bdst2 = sbase + ASZ + (128 + arow) * 80 + aq * 16;

    // ldmatrix fragment addresses
    const uint32_t afrag = sbase + (wm * 16 + (lane & 15)) * 80 + (lane >> 4) * 16;
    const uint32_t bfrag = sbase + ASZ + (wn * 128 + (lane & 7)) * 80 + (lane >> 3) * 16;

    // preload chunk 0 -> stage 0
    cp16(adst, asrc, aok);
    cp16(bdst1, bsrc1, true);
    cp16(bdst2, bsrc2, true);
    CP_COMMIT();

#pragma unroll 1
    for (int c = 0; c < NC; c++) {
        if (c + 1 < NC) {
            const uint32_t nso = ((c + 1) & 1) * STAGE;
            const int koff = (c + 1) * 32;
            cp16(adst + nso, asrc + koff, aok);
            cp16(bdst1 + nso, bsrc1 + koff, true);
            cp16(bdst2 + nso, bsrc2 + koff, true);
            CP_COMMIT();
            CP_WAIT(1);
        } else {
            CP_WAIT(0);
        }
        __syncthreads();
        const uint32_t so = (c & 1) * STAGE;
        uint32_t a0[4], a1[4];
        LDSM4(a0, afrag + so);          // k 0..15
        LDSM4(a1, afrag + so + 32);     // k 16..31
        const uint32_t bb = bfrag + so;
#pragma unroll
        for (int ntl = 0; ntl < 16; ntl++) {
            uint32_t bq[4];
            LDSM4(bq, bb + ntl * 640);  // 4 matrices = k 0..31 for 8 n-rows
            MMA16816(acc[ntl], a0, bq[0], bq[1]);
            MMA16816(acc[ntl], a1, bq[2], bq[3]);
        }
        __syncthreads();
    }
}

// ---------------- fp32 GEMM core (small kernels) ----------------
__device__ __forceinline__ void gemm_core(
    const float* __restrict__ A, int lda, int Am, int m0,
    const float* __restrict__ Bp, int ldb, int n0, int bcol0,
    int Kd, float acc[8][8],
    float As[][BM], float Bs[][BN])
{
    const int tid = threadIdx.x;
    const int tx = tid & 31, ty = tid >> 5;
    const int lm = tid >> 2, lq = tid & 3;

    for (int k0 = 0; k0 < Kd; k0 += BKK) {
        float4 va = make_float4(0.f, 0.f, 0.f, 0.f);
        int gm = m0 + lm;
        if (gm < Am) va = *(const float4*)(A + (size_t)gm * lda + (k0 + lq * 4));
        As[lq * 4 + 0][lm] = va.x; As[lq * 4 + 1][lm] = va.y;
        As[lq * 4 + 2][lm] = va.z; As[lq * 4 + 3][lm] = va.w;
        const float* bp = Bp + (size_t)(n0 + tid) * ldb + bcol0 + k0;
#pragma unroll
        for (int q = 0; q < 4; q++) {
            float4 vb = *(const float4*)(bp + q * 4);
            Bs[q * 4 + 0][tid] = vb.x; Bs[q * 4 + 1][tid] = vb.y;
            Bs[q * 4 + 2][tid] = vb.z; Bs[q * 4 + 3][tid] = vb.w;
        }
        __syncthreads();
#pragma unroll
        for (int k = 0; k < BKK; k++) {
            float4 a0 = *(const float4*)&As[k][ty * 4];
            float4 a1 = *(const float4*)&As[k][32 + ty * 4];
            float4 b0 = *(const float4*)&Bs[k][tx * 4];
            float4 b1 = *(const float4*)&Bs[k][128 + tx * 4];
            float a[8] = {a0.x, a0.y, a0.z, a0.w, a1.x, a1.y, a1.z, a1.w};
            float b[8] = {b0.x, b0.y, b0.z, b0.w, b1.x, b1.y, b1.z, b1.w};
#pragma unroll
            for (int i = 0; i < 8; i++)
#pragma unroll
                for (int jj = 0; jj < 8; jj++)
                    acc[i][jj] = fmaf(a[i], b[jj], acc[i][jj]);
        }
        __syncthreads();
    }
}

// ---------------- kernel 1: emission MLP (writes fp32 + bf16 h) ----------------
__global__ __launch_bounds__(256, 2) void k_em_mlp(
    const float* __restrict__ lembs, const float* __restrict__ emW,
    const float* __restrict__ em_bias, const float* __restrict__ em_g,
    const float* __restrict__ em_beta)
{
    __shared__ float As[BKK][BM];
    __shared__ float Bs[BKK][BN];
    __shared__ float redS[BM][33];
    __shared__ float redQ[BM][33];
    __shared__ float2 stats[BM];

    const int tid = threadIdx.x;
    const int tx = tid & 31, ty = tid >> 5;
    const int m0 = blockIdx.x * BM;

    float acc[8][8];
#pragma unroll
    for (int i = 0; i < 8; i++)
#pragma unroll
        for (int j = 0; j < 8; j++) acc[i][j] = 0.f;

    gemm_core(lembs, D_, K_, m0, emW, D_, 0, 0, D_, acc, As, Bs);

    float rs[8], rq[8];
#pragma unroll
    for (int i = 0; i < 8; i++) { rs[i] = 0.f; rq[i] = 0.f; }
#pragma unroll
    for (int i = 0; i < 8; i++) {
        int gm = m0 + MI(i);
#pragma unroll
        for (int j = 0; j < 8; j++) {
            int nj = NJ(j);
            float v = lembs[gm * D_ + nj] + fmaxf(acc[i][j] + em_bias[nj], 0.f);
            acc[i][j] = v; rs[i] += v; rq[i] += v * v;
        }
    }
#pragma unroll
    for (int i = 0; i < 8; i++) { redS[MI(i)][tx] = rs[i]; redQ[MI(i)][tx] = rq[i]; }
    __syncthreads();
    if (tid < BM) {
        float s = 0.f, q = 0.f;
#pragma unroll
        for (int xX = 0; xX < 32; xX++) { s += redS[tid][xX]; q += redQ[tid][xX]; }
        float mu = s * (1.f / D_);
        float var = q * (1.f / D_) - mu * mu;
        stats[tid] = make_float2(mu, rsqrtf(var + EPS));
    }
    __syncthreads();
#pragma unroll
    for (int i = 0; i < 8; i++) {
        int mi = MI(i); int gm = m0 + mi;
        float2 st = stats[mi];
#pragma unroll
        for (int j = 0; j < 8; j++) {
            int nj = NJ(j);
            float v = (acc[i][j] - st.x) * st.y * em_g[nj] + em_beta[nj];
            g_h[gm * D_ + nj] = v;
            g_h_bf[gm * D_ + nj] = __float2bfloat16(v);
        }
    }
}

// ---------------- kernel 2: A_t / B_t ----------------
__global__ __launch_bounds__(256, 2) void k_t_pre(
    const float* __restrict__ tlembs, const float* __restrict__ tmW)
{
    __shared__ float As[BKK][BM];
    __shared__ float Bs[BKK][BN];
    const int tid = threadIdx.x;
    const int tx = tid & 31, ty = tid >> 5;
    const int m0 = blockIdx.x * BM;
    const int n0 = (blockIdx.y & 1) * 256;
    const int half = blockIdx.y >> 1;
    const int bcol0 = half * 256;

    float acc[8][8];
#pragma unroll
    for (int i = 0; i < 8; i++)
#pragma unroll
        for (int j = 0; j < 8; j++) acc[i][j] = 0.f;

    gemm_core(tlembs, D_, KP1, m0, tmW, MD, n0, bcol0, D_, acc, As, Bs);

    float* out = half ? g_Bt : g_At;
#pragma unroll
    for (int i = 0; i < 8; i++) {
        int gm = m0 + MI(i);
        if (gm < KP1) {
#pragma unroll
            for (int j = 0; j < 8; j++) out[gm * MD + n0 + NJ(j)] = acc[i][j];
        }
    }
}

// ---------------- conversion kernels ----------------
__global__ __launch_bounds__(256) void k_cvt_tdw(const float* __restrict__ tdW)
{
    int i = blockIdx.x * 256 + threadIdx.x;        // quad index
    if (i < K_ * MD / 4) {
        float4 f = *(const float4*)(tdW + i * 4);
        uint2 u; u.x = pack_bf2(f.x, f.y); u.y = pack_bf2(f.z, f.w);
        *(uint2*)(g_tdW_bf + i * 4) = u;
    }
}
__global__ __launch_bounds__(256) void k_cvt_decw(const float* __restrict__ decW)
{
    int i = blockIdx.x * 256 + threadIdx.x;        // quad index
    if (i < V_ * D_ / 4) {
        float4 f = *(const float4*)(decW + (size_t)i * 4);
        uint2 u; u.x = pack_bf2(f.x, f.y); u.y = pack_bf2(f.z, f.w);
        *(uint2*)(g_decW_bf + (size_t)i * 4) = u;
    }
}

// ---------------- kernel 3: th (bf16 out) ----------------
__global__ __launch_bounds__(256) void k_th(
    const float* __restrict__ tlembs, const float* __restrict__ tm_bias,
    const float* __restrict__ tn_g, const float* __restrict__ tn_beta)
{
    const int r = blockIdx.x;
    const int i = r / KP1, j = r % KP1;
    __shared__ float y[MD];
    __shared__ float red[16];
    __shared__ float2 st;
    const int tid = threadIdx.x;
    const int lane = tid & 31, warp = tid >> 5;

    float s = 0.f, q = 0.f;
#pragma unroll
    for (int e0 = 0; e0 < MD; e0 += 256) {
        int e = e0 + tid;
        float c = (e < D_) ? tlembs[i * D_ + e] : tlembs[j * D_ + (e - D_)];
        float pre = g_At[i * MD + e] + g_Bt[j * MD + e] + tm_bias[e];
        float v = c + fmaxf(pre, 0.f);
        y[e] = v; s += v; q += v * v;
    }
#pragma unroll
    for (int o = 16; o; o >>= 1) {
        s += __shfl_xor_sync(0xffffffffu, s, o);
        q += __shfl_xor_sync(0xffffffffu, q, o);
    }
    if (lane == 0) { red[warp] = s; red[8 + warp] = q; }
    __syncthreads();
    if (tid == 0) {
        float S = 0.f, Q = 0.f;
#pragma unroll
        for (int w = 0; w < 8; w++) { S += red[w]; Q += red[8 + w]; }
        float mu = S * (1.f / MD);
        st = make_float2(mu, rsqrtf(Q * (1.f / MD) - mu * mu + EPS));
    }
    __syncthreads();
    float2 stt = st;
#pragma unroll
    for (int e0 = 0; e0 < MD; e0 += 256) {
        int e = e0 + tid;
        g_th_bf[(size_t)r * MD + e] =
            __float2bfloat16((y[e] - stt.x) * stt.y * tn_g[e] + tn_beta[e]);
    }
}

// ---------------- kernel 4: emission lse GEMM (HMMA) ----------------
// partial[blk][k] = sum_{v in tile} exp(decW_bf[v] . h_bf[k] + decb[v])
__global__ __launch_bounds__(512) void k_em_mma(const float* __restrict__ decb)
{
    extern __shared__ char smc[];
    const uint32_t sbase = s2u(smc);
    const int tid = threadIdx.x;
    const int lane = tid & 31, wid = tid >> 5;
    const int wm = wid & 7, wn = wid >> 3;
    const int m0 = blockIdx.x * 128;

    float acc[16][4];
#pragma unroll
    for (int i = 0; i < 16; i++)
#pragma unroll
        for (int j = 0; j < 4; j++) acc[i][j] = 0.f;

    mma_pipeline(g_decW_bf, D_, V_, g_h_bf, D_, D_ / 32, m0, sbase, acc);

    // epilogue: column sums of exp(acc + decb[row])
    const int r1 = m0 + wm * 16 + (lane >> 2);
    const int r2 = r1 + 8;
    const bool ok1 = r1 < V_, ok2 = r2 < V_;
    const float b1 = ok1 ? __ldg(&decb[r1]) : 0.f;
    const float b2 = ok2 ? __ldg(&decb[r2]) : 0.f;
    float* cps = (float*)smc;   // [256][8]
#pragma unroll
    for (int ntl = 0; ntl < 16; ntl++) {
        float v0 = (ok1 ? __expf(acc[ntl][0] + b1) : 0.f) + (ok2 ? __expf(acc[ntl][2] + b2) : 0.f);
        float v1 = (ok1 ? __expf(acc[ntl][1] + b1) : 0.f) + (ok2 ? __expf(acc[ntl][3] + b2) : 0.f);
#pragma unroll
        for (int o = 4; o < 32; o <<= 1) {
            v0 += __shfl_xor_sync(0xffffffffu, v0, o);
            v1 += __shfl_xor_sync(0xffffffffu, v1, o);
        }
        if (lane < 4) {
            int c0 = wn * 128 + ntl * 8 + 2 * lane;
            cps[c0 * 8 + wm] = v0;
            cps[(c0 + 1) * 8 + wm] = v1;
        }
    }
    __syncthreads();
    if (tid < 256) {
        float s = 0.f;
#pragma unroll
        for (int w = 0; w < 8; w++) s += cps[tid * 8 + w];
        g_part_em[blockIdx.x * K_ + tid] = s;
    }
}

// ---------------- kernel 5: reduce emission partials ----------------
__global__ __launch_bounds__(256) void k_red_em()
{
    const int k = threadIdx.x;
    float s = 0.f;
    for (int c = 0; c < NVT; c++) s += g_part_em[c * K_ + k];
    g_lse_em[k] = __logf(s);
}

// ---------------- kernel 6: transition GEMM (HMMA) -> row lse only ----------------
__global__ __launch_bounds__(512) void k_tr_mma(const float* __restrict__ tdb)
{
    extern __shared__ char smc[];
    const uint32_t sbase = s2u(smc);
    const int tid = threadIdx.x;
    const int lane = tid & 31, wid = tid >> 5;
    const int wm = wid & 7, wn = wid >> 3;
    const int m0 = blockIdx.x * 128;

    float acc[16][4];
#pragma unroll
    for (int i = 0; i < 16; i++)
#pragma unroll
        for (int j = 0; j < 4; j++) acc[i][j] = 0.f;

    mma_pipeline(g_th_bf, MD, R2, g_tdW_bf, MD, MD / 32, m0, sbase, acc);

    // epilogue: row sums of exp(acc + tdb[col]) -> lse
    float e1 = 0.f, e2 = 0.f;
    const int colb = wn * 128 + 2 * (lane & 3);
#pragma unroll
    for (int ntl = 0; ntl < 16; ntl++) {
        int cb = colb + ntl * 8;
        float t0 = __ldg(&tdb[cb]), t1 = __ldg(&tdb[cb + 1]);
        e1 += __expf(acc[ntl][0] + t0) + __expf(acc[ntl][1] + t1);
        e2 += __expf(acc[ntl][2] + t0) + __expf(acc[ntl][3] + t1);
    }
#pragma unroll
    for (int o = 1; o < 4; o <<= 1) {
        e1 += __shfl_xor_sync(0xffffffffu, e1, o);
        e2 += __shfl_xor_sync(0xffffffffu, e2, o);
    }
    float* rps = (float*)smc;   // [128][2]
    if ((lane & 3) == 0) {
        int lr = wm * 16 + (lane >> 2);
        rps[lr * 2 + wn] = e1;
        rps[(lr + 8) * 2 + wn] = e2;
    }
    __syncthreads();
    if (tid < 128) {
        int gm = m0 + tid;
        if (gm < R2) g_lseT[gm] = __logf(rps[tid * 2] + rps[tid * 2 + 1]);
    }
}

// ---------------- kernel 7: final scoring (recomputes needed trans logits) ----------------
__global__ __launch_bounds__(256) void k_final(
    const int* __restrict__ x, const int* __restrict__ z,
    const float* __restrict__ decW, const float* __restrict__ decb,
    const float* __restrict__ tdb, float* __restrict__ out)
{
    const int b = blockIdx.x;
    const int tid = threadIdx.x;
    const int lane = tid & 31, warp = tid >> 5;
    float acc = 0.f;

    for (int t = warp; t < T_; t += 8) {
        int zt = z[t * B_ + b];
        int xt = x[t * B_ + b];
        // emission logit: fp32 h . decW row
        const float* hv = g_h + zt * D_;
        const float* wv = decW + (size_t)xt * D_;
        float s = 0.f;
#pragma unroll
        for (int q = 0; q < 2; q++) {
            float4 hh = *(const float4*)&hv[lane * 4 + q * 128];
            float4 ww = *(const float4*)&wv[lane * 4 + q * 128];
            s += hh.x * ww.x + hh.y * ww.y + hh.z * ww.z + hh.w * ww.w;
        }
        // transition logit: bf16 th[lin] . tdW[zt]
        int zp1 = (t >= 1) ? z[(t - 1) * B_ + b] : K_;
        int zp2 = (t >= 2) ? z[(t - 2) * B_ + b] : K_;
        int lin = zp2 * KP1 + zp1;
        const uint4* thp = (const uint4*)(g_th_bf + (size_t)lin * MD);
        const uint4* twp = (const uint4*)(g_tdW_bf + (size_t)zt * MD);
#pragma unroll
        for (int q = 0; q < 2; q++) {
            uint4 aa = thp[lane + q * 32];
            uint4 ww = twp[lane + q * 32];
            s += dotu(aa.x, ww.x) + dotu(aa.y, ww.y) + dotu(aa.z, ww.z) + dotu(aa.w, ww.w);
        }
#pragma unroll
        for (int o = 16; o; o >>= 1) s += __shfl_xor_sync(0xffffffffu, s, o);
        if (lane == 0)
            acc += s + decb[xt] + tdb[zt] - g_lse_em[zt] - g_lseT[lin];
    }
    __shared__ float red[256];
    red[tid] = acc;
    __syncthreads();
    for (int st = 128; st; st >>= 1) {
        if (tid < st) red[tid] += red[tid + st];
        __syncthreads();
    }
    if (tid == 0) out[b] = red[0];
}

// ---------------- launch ----------------
extern "C" void kernel_launch(void* const* d_in, const int* in_sizes, int n_in,
                              void* d_out, int out_size)
{
    (void)in_sizes; (void)n_in; (void)out_size;
    const int*   x       = (const int*)d_in[0];
    const int*   z       = (const int*)d_in[1];
    const float* lembs   = (const float*)d_in[2];
    const float* tlembs  = (const float*)d_in[3];
    const float* decW    = (const float*)d_in[4];
    const float* decb    = (const float*)d_in[5];
    const float* emW     = (const float*)d_in[6];
    const float* em_bias = (const float*)d_in[7];
    const float* em_g    = (const float*)d_in[8];
    const float* em_beta = (const float*)d_in[9];
    const float* tdW     = (const float*)d_in[10];
    const float* tdb     = (const float*)d_in[11];
    const float* tmW     = (const float*)d_in[12];
    const float* tm_bias = (const float*)d_in[13];
    const float* tn_g    = (const float*)d_in[14];
    const float* tn_beta = (const float*)d_in[15];
    float* out = (float*)d_out;

    cudaFuncSetAttribute(k_em_mma, cudaFuncAttributeMaxDynamicSharedMemorySize, SMEMSZ);
    cudaFuncSetAttribute(k_tr_mma, cudaFuncAttributeMaxDynamicSharedMemorySize, SMEMSZ);

    k_em_mlp<<<K_ / BM, 256>>>(lembs, emW, em_bias, em_g, em_beta);
    k_t_pre<<<dim3((KP1 + BM - 1) / BM, 4), 256>>>(tlembs, tmW);
    k_cvt_tdw<<<(K_ * MD / 4 + 255) / 256, 256>>>(tdW);
    k_cvt_decw<<<(V_ * D_ / 4 + 255) / 256, 256>>>(decW);
    k_th<<<R2, 256>>>(tlembs, tm_bias, tn_g, tn_beta);
    k_em_mma<<<NVT, 512, SMEMSZ>>>(decb);
    k_red_em<<<1, 256>>>();
    k_tr_mma<<<NRT, 512, SMEMSZ>>>(tdb);
    k_final<<<B_, 256>>>(x, z, decW, decb, tdb, out);
}

// round 7
// speedup vs baseline: 1.6009x; 1.6009x over previous
#include <cuda_runtime.h>
#include <cuda_bf16.h>
#include <math.h>
#include <stdint.h>

// ---------------- problem constants ----------------
#define K_   256
#define KP1  257
#define D_   256
#define V_   50000
#define T_   512
#define B_   256
#define MD   512              // M*D
#define R2   66049            // KP1*KP1
#define EPS  1e-5f

#define NRT  517              // ceil(R2/128)
#define NVT  391              // ceil(V/128)

// ---------------- scratch ----------------
__device__ __nv_bfloat16 g_h_bf[K_ * D_];
__device__ float g_lse_em[K_];
__device__ float g_part_em[NVT * K_];
__device__ float g_At[KP1 * MD];
__device__ float g_Bt[KP1 * MD];
__device__ __nv_bfloat16 g_th_bf[(size_t)R2 * MD];   // 67.6 MB
__device__ float g_lseT[R2];
__device__ float g_out_part[4 * B_];
// bf16 copies of weights
__device__ __nv_bfloat16 g_lembs_bf[K_ * D_];
__device__ __nv_bfloat16 g_emW_bf[D_ * D_];
__device__ __nv_bfloat16 g_tlembs_bf[KP1 * D_];
__device__ __nv_bfloat16 g_tmW_bf[MD * MD];
__device__ __nv_bfloat16 g_tdW_bf[K_ * MD];
__device__ __nv_bfloat16 g_decW_bf[(size_t)V_ * D_]; // 25.6 MB

// ================= helpers =================
__device__ __forceinline__ uint32_t s2u(const void* p) {
    uint32_t a;
    asm("{ .reg .u64 t; cvta.to.shared.u64 t, %1; cvt.u32.u64 %0, t; }" : "=r"(a) : "l"(p));
    return a;
}
__device__ __forceinline__ uint32_t pack_bf2(float a, float b) {
    uint32_t u;
    asm("cvt.rn.bf16x2.f32 %0, %1, %2;" : "=r"(u) : "f"(b), "f"(a));
    return u;
}
__device__ __forceinline__ float dotu(uint32_t a, uint32_t b) {
    float2 fa = __bfloat1622float2(*reinterpret_cast<const __nv_bfloat162*>(&a));
    float2 fb = __bfloat1622float2(*reinterpret_cast<const __nv_bfloat162*>(&b));
    return fa.x * fb.x + fa.y * fb.y;
}
__device__ __forceinline__ void cp16(uint32_t dst, const void* src, bool ok) {
    int sz = ok ? 16 : 0;
    asm volatile("cp.async.cg.shared.global [%0], [%1], 16, %2;"
                 :: "r"(dst), "l"(src), "r"(sz) : "memory");
}
#define CP_COMMIT() asm volatile("cp.async.commit_group;" ::: "memory")
#define CP_WAIT(n)  asm volatile("cp.async.wait_group %0;" :: "n"(n) : "memory")

#define LDSM4(r, addr) \
    asm volatile("ldmatrix.sync.aligned.m8n8.x4.shared.b16 {%0,%1,%2,%3}, [%4];" \
                 : "=r"((r)[0]), "=r"((r)[1]), "=r"((r)[2]), "=r"((r)[3]) : "r"(addr))

#define MMA16816(c, a, b0v, b1v) \
    asm volatile("mma.sync.aligned.m16n8k16.row.col.f32.bf16.bf16.f32 " \
                 "{%0,%1,%2,%3}, {%4,%5,%6,%7}, {%8,%9}, {%0,%1,%2,%3};" \
                 : "+f"((c)[0]), "+f"((c)[1]), "+f"((c)[2]), "+f"((c)[3]) \
                 : "r"((a)[0]), "r"((a)[1]), "r"((a)[2]), "r"((a)[3]), "r"(b0v), "r"(b1v))

// smem stage layout: A 128 rows x 80B = 10240, B 256 rows x 80B = 20480
#define ASZ    10240
#define STAGE  30720
#define SMEMSZ (2 * STAGE)

// ---------------- HMMA pipeline core ----------------
// C[128 x 256] tile: A rows m0.., B rows 0..255 of Bptr; NC chunks of K=32.
// 512 threads, 16 warps: wm = wid&7 (16-row slice), wn = wid>>3 (128-col half).
__device__ __forceinline__ void mma_pipeline(
    const __nv_bfloat16* __restrict__ Aptr, int lda, int AM,
    const __nv_bfloat16* __restrict__ Bptr, int ldb,
    int NC, int m0, uint32_t sbase, float acc[16][4])
{
    const int tid = threadIdx.x;
    const int lane = tid & 31, wid = tid >> 5;
    const int wm = wid & 7, wn = wid >> 3;

    const int arow = tid >> 2, aq = tid & 3;
    const int gmA = m0 + arow;
    const bool aok = gmA < AM;
    const __nv_bfloat16* asrc = Aptr + (size_t)(aok ? gmA : 0) * lda + aq * 8;
    const __nv_bfloat16* bsrc1 = Bptr + (size_t)arow * ldb + aq * 8;
    const __nv_bfloat16* bsrc2 = Bptr + (size_t)(128 + arow) * ldb + aq * 8;
    const uint32_t adst  = sbase + arow * 80 + aq * 16;
    const uint32_t bdst1 = sbase + ASZ + arow * 80 + aq * 16;
    const uint32_t bdst2 = sbase + ASZ + (128 + arow) * 80 + aq * 16;

    const uint32_t afrag = sbase + (wm * 16 + (lane & 15)) * 80 + (lane >> 4) * 16;
    const uint32_t bfrag = sbase + ASZ + (wn * 128 + (lane & 7)) * 80 + (lane >> 3) * 16;

    cp16(adst, asrc, aok);
    cp16(bdst1, bsrc1, true);
    cp16(bdst2, bsrc2, true);
    CP_COMMIT();

#pragma unroll 1
    for (int c = 0; c < NC; c++) {
        if (c + 1 < NC) {
            const uint32_t nso = ((c + 1) & 1) * STAGE;
            const int koff = (c + 1) * 32;
            cp16(adst + nso, asrc + koff, aok);
            cp16(bdst1 + nso, bsrc1 + koff, true);
            cp16(bdst2 + nso, bsrc2 + koff, true);
            CP_COMMIT();
            CP_WAIT(1);
        } else {
            CP_WAIT(0);
        }
        __syncthreads();
        const uint32_t so = (c & 1) * STAGE;
        uint32_t a0[4], a1[4];
        LDSM4(a0, afrag + so);
        LDSM4(a1, afrag + so + 32);
        const uint32_t bb = bfrag + so;
#pragma unroll
        for (int ntl = 0; ntl < 16; ntl++) {
            uint32_t bq[4];
            LDSM4(bq, bb + ntl * 640);
            MMA16816(acc[ntl], a0, bq[0], bq[1]);
            MMA16816(acc[ntl], a1, bq[2], bq[3]);
        }
        __syncthreads();
    }
}

// ---------------- generic fp32 -> bf16 conversion ----------------
__global__ __launch_bounds__(256) void k_cvt(const float* __restrict__ src,
                                             __nv_bfloat16* __restrict__ dst, int nq)
{
    int i = blockIdx.x * 256 + threadIdx.x;
    if (i < nq) {
        float4 f = *(const float4*)(src + (size_t)i * 4);
        uint2 u; u.x = pack_bf2(f.x, f.y); u.y = pack_bf2(f.z, f.w);
        *(uint2*)(dst + (size_t)i * 4) = u;
    }
}

// ---------------- kernel 1: emission MLP (HMMA) -> g_h_bf ----------------
__global__ __launch_bounds__(512) void k_em_mlp_mma(
    const float* __restrict__ lembs, const float* __restrict__ em_bias,
    const float* __restrict__ em_g, const float* __restrict__ em_beta)
{
    extern __shared__ char smc[];
    const uint32_t sbase = s2u(smc);
    const int tid = threadIdx.x;
    const int lane = tid & 31, wid = tid >> 5;
    const int wm = wid & 7, wn = wid >> 3;
    const int m0 = blockIdx.x * 128;

    float acc[16][4];
#pragma unroll
    for (int i = 0; i < 16; i++)
#pragma unroll
        for (int j = 0; j < 4; j++) acc[i][j] = 0.f;

    mma_pipeline(g_lembs_bf, D_, K_, g_emW_bf, D_, D_ / 32, m0, sbase, acc);

    // epilogue: v = lembs + relu(acc + bias); LN(v)
    const int r1 = wm * 16 + (lane >> 2);
    const int r2 = r1 + 8;
    const int gm1 = m0 + r1, gm2 = m0 + r2;
    float s1 = 0.f, q1 = 0.f, s2 = 0.f, q2 = 0.f;
#pragma unroll
    for (int ntl = 0; ntl < 16; ntl++) {
        int cb = wn * 128 + ntl * 8 + 2 * (lane & 3);
        float2 b2v = *(const float2*)(em_bias + cb);
        float2 l1 = *(const float2*)(lembs + gm1 * D_ + cb);
        float2 l2 = *(const float2*)(lembs + gm2 * D_ + cb);
        float v0 = l1.x + fmaxf(acc[ntl][0] + b2v.x, 0.f);
        float v1 = l1.y + fmaxf(acc[ntl][1] + b2v.y, 0.f);
        float v2 = l2.x + fmaxf(acc[ntl][2] + b2v.x, 0.f);
        float v3 = l2.y + fmaxf(acc[ntl][3] + b2v.y, 0.f);
        acc[ntl][0] = v0; acc[ntl][1] = v1; acc[ntl][2] = v2; acc[ntl][3] = v3;
        s1 += v0 + v1; q1 += v0 * v0 + v1 * v1;
        s2 += v2 + v3; q2 += v2 * v2 + v3 * v3;
    }
#pragma unroll
    for (int o = 1; o < 4; o <<= 1) {
        s1 += __shfl_xor_sync(0xffffffffu, s1, o); q1 += __shfl_xor_sync(0xffffffffu, q1, o);
        s2 += __shfl_xor_sync(0xffffffffu, s2, o); q2 += __shfl_xor_sync(0xffffffffu, q2, o);
    }
    float* sS = (float*)smc;              // [128][2]
    float* sQ = (float*)smc + 256;        // [128][2]
    if ((lane & 3) == 0) {
        sS[r1 * 2 + wn] = s1; sQ[r1 * 2 + wn] = q1;
        sS[r2 * 2 + wn] = s2; sQ[r2 * 2 + wn] = q2;
    }
    __syncthreads();
    float mu1 = (sS[r1 * 2] + sS[r1 * 2 + 1]) * (1.f / D_);
    float rs1 = rsqrtf((sQ[r1 * 2] + sQ[r1 * 2 + 1]) * (1.f / D_) - mu1 * mu1 + EPS);
    float mu2 = (sS[r2 * 2] + sS[r2 * 2 + 1]) * (1.f / D_);
    float rs2 = rsqrtf((sQ[r2 * 2] + sQ[r2 * 2 + 1]) * (1.f / D_) - mu2 * mu2 + EPS);
#pragma unroll
    for (int ntl = 0; ntl < 16; ntl++) {
        int cb = wn * 128 + ntl * 8 + 2 * (lane & 3);
        float2 gg = *(const float2*)(em_g + cb);
        float2 bt = *(const float2*)(em_beta + cb);
        float h0 = (acc[ntl][0] - mu1) * rs1 * gg.x + bt.x;
        float h1 = (acc[ntl][1] - mu1) * rs1 * gg.y + bt.y;
        float h2 = (acc[ntl][2] - mu2) * rs2 * gg.x + bt.x;
        float h3 = (acc[ntl][3] - mu2) * rs2 * gg.y + bt.y;
        *(uint32_t*)(g_h_bf + gm1 * D_ + cb) = pack_bf2(h0, h1);
        *(uint32_t*)(g_h_bf + gm2 * D_ + cb) = pack_bf2(h2, h3);
    }
}

// ---------------- kernel 2: A_t / B_t (HMMA) ----------------
__global__ __launch_bounds__(512) void k_t_pre_mma()
{
    extern __shared__ char smc[];
    const uint32_t sbase = s2u(smc);
    const int tid = threadIdx.x;
    const int lane = tid & 31, wid = tid >> 5;
    const int wm = wid & 7, wn = wid >> 3;
    const int m0 = blockIdx.x * 128;
    const int n0 = (blockIdx.y & 1) * 256;
    const int half = blockIdx.y >> 1;
    const int bcol0 = half * 256;

    float acc[16][4];
#pragma unroll
    for (int i = 0; i < 16; i++)
#pragma unroll
        for (int j = 0; j < 4; j++) acc[i][j] = 0.f;

    mma_pipeline(g_tlembs_bf, D_, KP1,
                 g_tmW_bf + (size_t)n0 * MD + bcol0, MD, 256 / 32, m0, sbase, acc);

    float* out = half ? g_Bt : g_At;
    const int r1 = wm * 16 + (lane >> 2);
    const int gm1 = m0 + r1, gm2 = gm1 + 8;
#pragma unroll
    for (int ntl = 0; ntl < 16; ntl++) {
        int cb = n0 + wn * 128 + ntl * 8 + 2 * (lane & 3);
        if (gm1 < KP1) *(float2*)(out + gm1 * MD + cb) = make_float2(acc[ntl][0], acc[ntl][1]);
        if (gm2 < KP1) *(float2*)(out + gm2 * MD + cb) = make_float2(acc[ntl][2], acc[ntl][3]);
    }
}

// ---------------- kernel 3: th, one warp per row ----------------
__global__ __launch_bounds__(256) void k_th(
    const float* __restrict__ tlembs, const float* __restrict__ tm_bias,
    const float* __restrict__ tn_g, const float* __restrict__ tn_beta)
{
    const int tid = threadIdx.x;
    const int lane = tid & 31, warp = tid >> 5;
    const int r = blockIdx.x * 8 + warp;
    if (r >= R2) return;
    const int i = r / KP1, j = r % KP1;

    float v[16];
    float s = 0.f, q = 0.f;
#pragma unroll
    for (int qq = 0; qq < 4; qq++) {
        int e = 4 * (lane + 32 * qq);
        float4 c = (qq < 2) ? *(const float4*)(tlembs + i * D_ + e)
                            : *(const float4*)(tlembs + j * D_ + (e - D_));
        float4 a = *(const float4*)(g_At + i * MD + e);
        float4 b = *(const float4*)(g_Bt + j * MD + e);
        float4 bi = *(const float4*)(tm_bias + e);
        float v0 = c.x + fmaxf(a.x + b.x + bi.x, 0.f);
        float v1 = c.y + fmaxf(a.y + b.y + bi.y, 0.f);
        float v2 = c.z + fmaxf(a.z + b.z + bi.z, 0.f);
        float v3 = c.w + fmaxf(a.w + b.w + bi.w, 0.f);
        v[qq * 4 + 0] = v0; v[qq * 4 + 1] = v1; v[qq * 4 + 2] = v2; v[qq * 4 + 3] = v3;
        s += v0 + v1 + v2 + v3;
        q += v0 * v0 + v1 * v1 + v2 * v2 + v3 * v3;
    }
#pragma unroll
    for (int o = 16; o; o >>= 1) {
        s += __shfl_xor_sync(0xffffffffu, s, o);
        q += __shfl_xor_sync(0xffffffffu, q, o);
    }
    float mu = s * (1.f / MD);
    float rstd = rsqrtf(q * (1.f / MD) - mu * mu + EPS);
#pragma unroll
    for (int qq = 0; qq < 4; qq++) {
        int e = 4 * (lane + 32 * qq);
        float4 gg = *(const float4*)(tn_g + e);
        float4 bt = *(const float4*)(tn_beta + e);
        float h0 = (v[qq * 4 + 0] - mu) * rstd * gg.x + bt.x;
        float h1 = (v[qq * 4 + 1] - mu) * rstd * gg.y + bt.y;
        float h2 = (v[qq * 4 + 2] - mu) * rstd * gg.z + bt.z;
        float h3 = (v[qq * 4 + 3] - mu) * rstd * gg.w + bt.w;
        uint2 u; u.x = pack_bf2(h0, h1); u.y = pack_bf2(h2, h3);
        *(uint2*)(g_th_bf + (size_t)r * MD + e) = u;
    }
}

// ---------------- kernel 4: emission lse GEMM (HMMA) ----------------
__global__ __launch_bounds__(512) void k_em_mma(const float* __restrict__ decb)
{
    extern __shared__ char smc[];
    const uint32_t sbase = s2u(smc);
    const int tid = threadIdx.x;
    const int lane = tid & 31, wid = tid >> 5;
    const int wm = wid & 7, wn = wid >> 3;
    const int m0 = blockIdx.x * 128;

    float acc[16][4];
#pragma unroll
    for (int i = 0; i < 16; i++)
#pragma unroll
        for (int j = 0; j < 4; j++) acc[i][j] = 0.f;

    mma_pipeline(g_decW_bf, D_, V_, g_h_bf, D_, D_ / 32, m0, sbase, acc);

    const int r1 = m0 + wm * 16 + (lane >> 2);
    const int r2 = r1 + 8;
    const bool ok1 = r1 < V_, ok2 = r2 < V_;
    const float b1 = ok1 ? __ldg(&decb[r1]) : 0.f;
    const float b2 = ok2 ? __ldg(&decb[r2]) : 0.f;
    float* cps = (float*)smc;   // [256][8]
#pragma unroll
    for (int ntl = 0; ntl < 16; ntl++) {
        float v0 = (ok1 ? __expf(acc[ntl][0] + b1) : 0.f) + (ok2 ? __expf(acc[ntl][2] + b2) : 0.f);
        float v1 = (ok1 ? __expf(acc[ntl][1] + b1) : 0.f) + (ok2 ? __expf(acc[ntl][3] + b2) : 0.f);
#pragma unroll
        for (int o = 4; o < 32; o <<= 1) {
            v0 += __shfl_xor_sync(0xffffffffu, v0, o);
            v1 += __shfl_xor_sync(0xffffffffu, v1, o);
        }
        if (lane < 4) {
            int c0 = wn * 128 + ntl * 8 + 2 * lane;
            cps[c0 * 8 + wm] = v0;
            cps[(c0 + 1) * 8 + wm] = v1;
        }
    }
    __syncthreads();
    if (tid < 256) {
        float s = 0.f;
#pragma unroll
        for (int w = 0; w < 8; w++) s += cps[tid * 8 + w];
        g_part_em[blockIdx.x * K_ + tid] = s;
    }
}

// ---------------- kernel 5: reduce emission partials (parallel) ----------------
__global__ __launch_bounds__(128) void k_red_em()
{
    const int k = blockIdx.x;
    const int tid = threadIdx.x;
    __shared__ float red[128];
    float s = 0.f;
    for (int c = tid; c < NVT; c += 128) s += g_part_em[c * K_ + k];
    red[tid] = s;
    __syncthreads();
    for (int st = 64; st; st >>= 1) {
        if (tid < st) red[tid] += red[tid + st];
        __syncthreads();
    }
    if (tid == 0) g_lse_em[k] = __logf(red[0]);
}

// ---------------- kernel 6: transition GEMM (HMMA) -> row lse only ----------------
__global__ __launch_bounds__(512) void k_tr_mma(const float* __restrict__ tdb)
{
    extern __shared__ char smc[];
    const uint32_t sbase = s2u(smc);
    const int tid = threadIdx.x;
    const int lane = tid & 31, wid = tid >> 5;
    const int wm = wid & 7, wn = wid >> 3;
    const int m0 = blockIdx.x * 128;

    float acc[16][4];
#pragma unroll
    for (int i = 0; i < 16; i++)
#pragma unroll
        for (int j = 0; j < 4; j++) acc[i][j] = 0.f;

    mma_pipeline(g_th_bf, MD, R2, g_tdW_bf, MD, MD / 32, m0, sbase, acc);

    float e1 = 0.f, e2 = 0.f;
    const int colb = wn * 128 + 2 * (lane & 3);
#pragma unroll
    for (int ntl = 0; ntl < 16; ntl++) {
        int cb = colb + ntl * 8;
        float t0 = __ldg(&tdb[cb]), t1 = __ldg(&tdb[cb + 1]);
        e1 += __expf(acc[ntl][0] + t0) + __expf(acc[ntl][1] + t1);
        e2 += __expf(acc[ntl][2] + t0) + __expf(acc[ntl][3] + t1);
    }
#pragma unroll
    for (int o = 1; o < 4; o <<= 1) {
        e1 += __shfl_xor_sync(0xffffffffu, e1, o);
        e2 += __shfl_xor_sync(0xffffffffu, e2, o);
    }
    float* rps = (float*)smc;   // [128][2]
    if ((lane & 3) == 0) {
        int lr = wm * 16 + (lane >> 2);
        rps[lr * 2 + wn] = e1;
        rps[(lr + 8) * 2 + wn] = e2;
    }
    __syncthreads();
    if (tid < 128) {
        int gm = m0 + tid;
        if (gm < R2) g_lseT[gm] = __logf(rps[tid * 2] + rps[tid * 2 + 1]);
    }
}

// ---------------- kernel 7: final scoring (bf16 gathers, T split 4) ----------------
__global__ __launch_bounds__(256) void k_final(
    const int* __restrict__ x, const int* __restrict__ z,
    const float* __restrict__ decb, const float* __restrict__ tdb)
{
    const int b = blockIdx.x;
    const int ts = blockIdx.y;
    const int tid = threadIdx.x;
    const int lane = tid & 31, warp = tid >> 5;
    float acc = 0.f;

    for (int tl = warp; tl < 128; tl += 8) {
        int t = ts * 128 + tl;
        int zt = z[t * B_ + b];
        int xt = x[t * B_ + b];
        // emission logit: bf16 h . decW_bf row (256 elems, 1 uint4/lane)
        const uint4* hp = (const uint4*)(g_h_bf + zt * D_);
        const uint4* wp = (const uint4*)(g_decW_bf + (size_t)xt * D_);
        uint4 hh = hp[lane], ww = wp[lane];
        float s = dotu(hh.x, ww.x) + dotu(hh.y, ww.y) + dotu(hh.z, ww.z) + dotu(hh.w, ww.w);
        // transition logit: bf16 th[lin] . tdW[zt] (512 elems, 2 uint4/lane)
        int zp1 = (t >= 1) ? z[(t - 1) * B_ + b] : K_;
        int zp2 = (t >= 2) ? z[(t - 2) * B_ + b] : K_;
        int lin = zp2 * KP1 + zp1;
        const uint4* thp = (const uint4*)(g_th_bf + (size_t)lin * MD);
        const uint4* twp = (const uint4*)(g_tdW_bf + (size_t)zt * MD);
#pragma unroll
        for (int q = 0; q < 2; q++) {
            uint4 aa = thp[lane + q * 32];
            uint4 bb = twp[lane + q * 32];
            s += dotu(aa.x, bb.x) + dotu(aa.y, bb.y) + dotu(aa.z, bb.z) + dotu(aa.w, bb.w);
        }
#pragma unroll
        for (int o = 16; o; o >>= 1) s += __shfl_xor_sync(0xffffffffu, s, o);
        if (lane == 0)
            acc += s + decb[xt] + tdb[zt] - g_lse_em[zt] - g_lseT[lin];
    }
    __shared__ float red[8];
    if (lane == 0) red[warp] = acc;
    __syncthreads();
    if (tid == 0) {
        float s = 0.f;
#pragma unroll
        for (int w = 0; w < 8; w++) s += red[w];
        g_out_part[ts * B_ + b] = s;
    }
}

// ---------------- kernel 8: final reduce ----------------
__global__ __launch_bounds__(256) void k_red_out(float* __restrict__ out)
{
    int b = threadIdx.x;
    out[b] = g_out_part[b] + g_out_part[B_ + b] + g_out_part[2 * B_ + b] + g_out_part[3 * B_ + b];
}

// ---------------- launch ----------------
extern "C" void kernel_launch(void* const* d_in, const int* in_sizes, int n_in,
                              void* d_out, int out_size)
{
    (void)in_sizes; (void)n_in; (void)out_size;
    const int*   x       = (const int*)d_in[0];
    const int*   z       = (const int*)d_in[1];
    const float* lembs   = (const float*)d_in[2];
    const float* tlembs  = (const float*)d_in[3];
    const float* decW    = (const float*)d_in[4];
    const float* decb    = (const float*)d_in[5];
    const float* emW     = (const float*)d_in[6];
    const float* em_bias = (const float*)d_in[7];
    const float* em_g    = (const float*)d_in[8];
    const float* em_beta = (const float*)d_in[9];
    const float* tdW     = (const float*)d_in[10];
    const float* tdb     = (const float*)d_in[11];
    const float* tmW     = (const float*)d_in[12];
    const float* tm_bias = (const float*)d_in[13];
    const float* tn_g    = (const float*)d_in[14];
    const float* tn_beta = (const float*)d_in[15];
    float* out = (float*)d_out;

    cudaFuncSetAttribute(k_em_mlp_mma, cudaFuncAttributeMaxDynamicSharedMemorySize, SMEMSZ);
    cudaFuncSetAttribute(k_t_pre_mma, cudaFuncAttributeMaxDynamicSharedMemorySize, SMEMSZ);
    cudaFuncSetAttribute(k_em_mma, cudaFuncAttributeMaxDynamicSharedMemorySize, SMEMSZ);
    cudaFuncSetAttribute(k_tr_mma, cudaFuncAttributeMaxDynamicSharedMemorySize, SMEMSZ);

    __nv_bfloat16 *p_lembs_bf, *p_emW_bf, *p_tlembs_bf, *p_tmW_bf, *p_tdW_bf, *p_decW_bf;
    cudaGetSymbolAddress((void**)&p_lembs_bf, g_lembs_bf);
    cudaGetSymbolAddress((void**)&p_emW_bf, g_emW_bf);
    cudaGetSymbolAddress((void**)&p_tlembs_bf, g_tlembs_bf);
    cudaGetSymbolAddress((void**)&p_tmW_bf, g_tmW_bf);
    cudaGetSymbolAddress((void**)&p_tdW_bf, g_tdW_bf);
    cudaGetSymbolAddress((void**)&p_decW_bf, g_decW_bf);

    k_cvt<<<(K_ * D_ / 4 + 255) / 256, 256>>>(lembs, p_lembs_bf, K_ * D_ / 4);
    k_cvt<<<(D_ * D_ / 4 + 255) / 256, 256>>>(emW, p_emW_bf, D_ * D_ / 4);
    k_cvt<<<(KP1 * D_ / 4 + 255) / 256, 256>>>(tlembs, p_tlembs_bf, KP1 * D_ / 4);
    k_cvt<<<(MD * MD / 4 + 255) / 256, 256>>>(tmW, p_tmW_bf, MD * MD / 4);
    k_cvt<<<(K_ * MD / 4 + 255) / 256, 256>>>(tdW, p_tdW_bf, K_ * MD / 4);
    k_cvt<<<(V_ * D_ / 4 + 255) / 256, 256>>>(decW, p_decW_bf, V_ * D_ / 4);

    k_em_mlp_mma<<<K_ / 128, 512, SMEMSZ>>>(lembs, em_bias, em_g, em_beta);
    k_t_pre_mma<<<dim3(3, 4), 512, SMEMSZ>>>();
    k_th<<<(R2 + 7) / 8, 256>>>(tlembs, tm_bias, tn_g, tn_beta);
    k_em_mma<<<NVT, 512, SMEMSZ>>>(decb);
    k_red_em<<<K_, 128>>>();
    k_tr_mma<<<NRT, 512, SMEMSZ>>>(tdb);
    k_final<<<dim3(B_, 4), 256>>>(x, z, decb, tdb);
    k_red_out<<<1, 256>>>(out);
}

// round 8
// speedup vs baseline: 1.6907x; 1.0561x over previous
#include <cuda_runtime.h>
#include <cuda_bf16.h>
#include <math.h>
#include <stdint.h>

// ---------------- problem constants ----------------
#define K_   256
#define KP1  257
#define D_   256
#define V_   50000
#define T_   512
#define B_   256
#define MD   512              // M*D
#define R2   66049            // KP1*KP1
#define EPS  1e-5f
#define NQ   (T_ * B_)        // 131072 queries

#define NRT  517              // ceil(R2/128)
#define NVT  391              // ceil(V/128)

// ---------------- scratch ----------------
__device__ __nv_bfloat16 g_h_bf[K_ * D_];
__device__ float g_lse_em[K_];
__device__ float g_part_em[NVT * K_];
__device__ float g_At[KP1 * MD];
__device__ float g_Bt[KP1 * MD];
// bf16 weights
__device__ __nv_bfloat16 g_lembs_bf[K_ * D_];
__device__ __nv_bfloat16 g_emW_bf[D_ * D_];
__device__ __nv_bfloat16 g_tlembs_bf[KP1 * D_];
__device__ __nv_bfloat16 g_tmW_bf[MD * MD];
__device__ __nv_bfloat16 g_tdW_bf[K_ * MD];
__device__ __nv_bfloat16 g_decW_bf[(size_t)V_ * D_];
// query machinery
__device__ int g_cnt_tr[R2];
__device__ int g_cur_tr[R2];
__device__ int g_qoff_tr[R2 + 1];
__device__ int g_cnt_em[V_];
__device__ int g_cur_em[V_];
__device__ int g_qoff_em[V_ + 1];
__device__ int g_bsum[512];
__device__ uint32_t g_qdat_tr[NQ];
__device__ uint32_t g_qdat_em[NQ];
__device__ float g_q_tr[NQ];
__device__ float g_q_em[NQ];

// ================= helpers =================
__device__ __forceinline__ uint32_t s2u(const void* p) {
    uint32_t a;
    asm("{ .reg .u64 t; cvta.to.shared.u64 t, %1; cvt.u32.u64 %0, t; }" : "=r"(a) : "l"(p));
    return a;
}
__device__ __forceinline__ uint32_t pack_bf2(float a, float b) {
    uint32_t u;
    asm("cvt.rn.bf16x2.f32 %0, %1, %2;" : "=r"(u) : "f"(b), "f"(a));
    return u;
}
__device__ __forceinline__ void cp16(uint32_t dst, const void* src, bool ok) {
    int sz = ok ? 16 : 0;
    asm volatile("cp.async.cg.shared.global [%0], [%1], 16, %2;"
                 :: "r"(dst), "l"(src), "r"(sz) : "memory");
}
#define CP_COMMIT() asm volatile("cp.async.commit_group;" ::: "memory")
#define CP_WAIT(n)  asm volatile("cp.async.wait_group %0;" :: "n"(n) : "memory")

#define LDSM4(r, addr) \
    asm volatile("ldmatrix.sync.aligned.m8n8.x4.shared.b16 {%0,%1,%2,%3}, [%4];" \
                 : "=r"((r)[0]), "=r"((r)[1]), "=r"((r)[2]), "=r"((r)[3]) : "r"(addr))

#define MMA16816(c, a, b0v, b1v) \
    asm volatile("mma.sync.aligned.m16n8k16.row.col.f32.bf16.bf16.f32 " \
                 "{%0,%1,%2,%3}, {%4,%5,%6,%7}, {%8,%9}, {%0,%1,%2,%3};" \
                 : "+f"((c)[0]), "+f"((c)[1]), "+f"((c)[2]), "+f"((c)[3]) \
                 : "r"((a)[0]), "r"((a)[1]), "r"((a)[2]), "r"((a)[3]), "r"(b0v), "r"(b1v))

// pipeline smem layout (em_mlp / t_pre / em_mma): A 128x80, B 256x80, 2 stages
#define ASZ    10240
#define STAGE  30720
#define SMEMSZ (2 * STAGE)
// em_mma: logits tile after stages
#define EM_LOG  61440
#define EM_SMEM (EM_LOG + 133120)
// tr_fused: resident A (th) tile 128 x 1040B; B stages; lse; rps
#define TRF_B0   133120
#define TRF_B1   153600
#define TRF_LSE  174080
#define TRF_RPS  174592
#define TRF_SMEM 175616

// ---------------- HMMA pipeline core (A+B staged) ----------------
__device__ __forceinline__ void mma_pipeline(
    const __nv_bfloat16* __restrict__ Aptr, int lda, int AM,
    const __nv_bfloat16* __restrict__ Bptr, int ldb,
    int NC, int m0, uint32_t sbase, float acc[16][4])
{
    const int tid = threadIdx.x;
    const int lane = tid & 31, wid = tid >> 5;
    const int wm = wid & 7, wn = wid >> 3;

    const int arow = tid >> 2, aq = tid & 3;
    const int gmA = m0 + arow;
    const bool aok = gmA < AM;
    const __nv_bfloat16* asrc = Aptr + (size_t)(aok ? gmA : 0) * lda + aq * 8;
    const __nv_bfloat16* bsrc1 = Bptr + (size_t)arow * ldb + aq * 8;
    const __nv_bfloat16* bsrc2 = Bptr + (size_t)(128 + arow) * ldb + aq * 8;
    const uint32_t adst  = sbase + arow * 80 + aq * 16;
    const uint32_t bdst1 = sbase + ASZ + arow * 80 + aq * 16;
    const uint32_t bdst2 = sbase + ASZ + (128 + arow) * 80 + aq * 16;

    const uint32_t afrag = sbase + (wm * 16 + (lane & 15)) * 80 + (lane >> 4) * 16;
    const uint32_t bfrag = sbase + ASZ + (wn * 128 + (lane & 7)) * 80 + (lane >> 3) * 16;

    cp16(adst, asrc, aok);
    cp16(bdst1, bsrc1, true);
    cp16(bdst2, bsrc2, true);
    CP_COMMIT();

#pragma unroll 1
    for (int c = 0; c < NC; c++) {
        if (c + 1 < NC) {
            const uint32_t nso = ((c + 1) & 1) * STAGE;
            const int koff = (c + 1) * 32;
            cp16(adst + nso, asrc + koff, aok);
            cp16(bdst1 + nso, bsrc1 + koff, true);
            cp16(bdst2 + nso, bsrc2 + koff, true);
            CP_COMMIT();
            CP_WAIT(1);
        } else {
            CP_WAIT(0);
        }
        __syncthreads();
        const uint32_t so = (c & 1) * STAGE;
        uint32_t a0[4], a1[4];
        LDSM4(a0, afrag + so);
        LDSM4(a1, afrag + so + 32);
        const uint32_t bb = bfrag + so;
#pragma unroll
        for (int ntl = 0; ntl < 16; ntl++) {
            uint32_t bq[4];
            LDSM4(bq, bb + ntl * 640);
            MMA16816(acc[ntl], a0, bq[0], bq[1]);
            MMA16816(acc[ntl], a1, bq[2], bq[3]);
        }
        __syncthreads();
    }
}

// ---------------- fp32 -> bf16 conversion ----------------
__global__ __launch_bounds__(256) void k_cvt(const float* __restrict__ src,
                                             __nv_bfloat16* __restrict__ dst, int nq)
{
    int i = blockIdx.x * 256 + threadIdx.x;
    if (i < nq) {
        float4 f = *(const float4*)(src + (size_t)i * 4);
        uint2 u; u.x = pack_bf2(f.x, f.y); u.y = pack_bf2(f.z, f.w);
        *(uint2*)(dst + (size_t)i * 4) = u;
    }
}

// ---------------- query index build ----------------
__global__ __launch_bounds__(256) void k_qzero()
{
    int i = blockIdx.x * 256 + threadIdx.x;
    int stride = gridDim.x * 256;
    for (int k = i; k < R2; k += stride) { g_cnt_tr[k] = 0; g_cur_tr[k] = 0; }
    for (int k = i; k < V_; k += stride) { g_cnt_em[k] = 0; g_cur_em[k] = 0; }
}

__global__ __launch_bounds__(256) void k_qcount(const int* __restrict__ x,
                                                const int* __restrict__ z)
{
    int idx = blockIdx.x * 256 + threadIdx.x;
    int t = idx >> 8;
    int zp1 = (t >= 1) ? z[idx - B_] : K_;
    int zp2 = (t >= 2) ? z[idx - 2 * B_] : K_;
    atomicAdd(&g_cnt_tr[zp2 * KP1 + zp1], 1);
    atomicAdd(&g_cnt_em[x[idx]], 1);
}

__global__ __launch_bounds__(256) void k_scan1(int which, int n)
{
    const int* cnt = which ? g_cnt_em : g_cnt_tr;
    __shared__ int sh[256];
    int i = blockIdx.x * 256 + threadIdx.x;
    sh[threadIdx.x] = (i < n) ? cnt[i] : 0;
    __syncthreads();
    for (int s = 128; s; s >>= 1) {
        if (threadIdx.x < s) sh[threadIdx.x] += sh[threadIdx.x + s];
        __syncthreads();
    }
    if (threadIdx.x == 0) g_bsum[blockIdx.x] = sh[0];
}

__global__ __launch_bounds__(512) void k_scan2(int nb)
{
    __shared__ int sh[512];
    int v = (threadIdx.x < nb) ? g_bsum[threadIdx.x] : 0;
    sh[threadIdx.x] = v;
    __syncthreads();
    for (int o = 1; o < 512; o <<= 1) {
        int t = (threadIdx.x >= o) ? sh[threadIdx.x - o] : 0;
        __syncthreads();
        sh[threadIdx.x] += t;
        __syncthreads();
    }
    if (threadIdx.x < nb) g_bsum[threadIdx.x] = sh[threadIdx.x] - v;  // exclusive
}

__global__ __launch_bounds__(256) void k_scan3(int which, int n)
{
    const int* cnt = which ? g_cnt_em : g_cnt_tr;
    int* qoff = which ? g_qoff_em : g_qoff_tr;
    __shared__ int sh[256];
    int i = blockIdx.x * 256 + threadIdx.x;
    int v = (i < n) ? cnt[i] : 0;
    sh[threadIdx.x] = v;
    __syncthreads();
    for (int o = 1; o < 256; o <<= 1) {
        int t = (threadIdx.x >= o) ? sh[threadIdx.x - o] : 0;
        __syncthreads();
        sh[threadIdx.x] += t;
        __syncthreads();
    }
    int incl = sh[threadIdx.x];
    int base = g_bsum[blockIdx.x];
    if (i < n) qoff[i] = base + incl - v;
    if (i == n - 1) qoff[n] = base + incl;
}

__global__ __launch_bounds__(256) void k_qfill(const int* __restrict__ x,
                                               const int* __restrict__ z)
{
    int idx = blockIdx.x * 256 + threadIdx.x;
    int t = idx >> 8;
    int zt = z[idx];
    int zp1 = (t >= 1) ? z[idx - B_] : K_;
    int zp2 = (t >= 2) ? z[idx - 2 * B_] : K_;
    int lin = zp2 * KP1 + zp1;
    uint32_t pk = (uint32_t)idx | ((uint32_t)zt << 17);
    int pos = g_qoff_tr[lin] + atomicAdd(&g_cur_tr[lin], 1);
    g_qdat_tr[pos] = pk;
    int xt = x[idx];
    pos = g_qoff_em[xt] + atomicAdd(&g_cur_em[xt], 1);
    g_qdat_em[pos] = pk;
}

// ---------------- kernel: emission MLP (HMMA) -> g_h_bf ----------------
__global__ __launch_bounds__(512) void k_em_mlp_mma(
    const float* __restrict__ lembs, const float* __restrict__ em_bias,
    const float* __restrict__ em_g, const float* __restrict__ em_beta)
{
    extern __shared__ char smc[];
    const uint32_t sbase = s2u(smc);
    const int tid = threadIdx.x;
    const int lane = tid & 31, wid = tid >> 5;
    const int wm = wid & 7, wn = wid >> 3;
    const int m0 = blockIdx.x * 128;

    float acc[16][4];
#pragma unroll
    for (int i = 0; i < 16; i++)
#pragma unroll
        for (int j = 0; j < 4; j++) acc[i][j] = 0.f;

    mma_pipeline(g_lembs_bf, D_, K_, g_emW_bf, D_, D_ / 32, m0, sbase, acc);

    const int r1 = wm * 16 + (lane >> 2);
    const int r2 = r1 + 8;
    const int gm1 = m0 + r1, gm2 = m0 + r2;
    float s1 = 0.f, q1 = 0.f, s2 = 0.f, q2 = 0.f;
#pragma unroll
    for (int ntl = 0; ntl < 16; ntl++) {
        int cb = wn * 128 + ntl * 8 + 2 * (lane & 3);
        float2 b2v = *(const float2*)(em_bias + cb);
        float2 l1 = *(const float2*)(lembs + gm1 * D_ + cb);
        float2 l2 = *(const float2*)(lembs + gm2 * D_ + cb);
        float v0 = l1.x + fmaxf(acc[ntl][0] + b2v.x, 0.f);
        float v1 = l1.y + fmaxf(acc[ntl][1] + b2v.y, 0.f);
        float v2 = l2.x + fmaxf(acc[ntl][2] + b2v.x, 0.f);
        float v3 = l2.y + fmaxf(acc[ntl][3] + b2v.y, 0.f);
        acc[ntl][0] = v0; acc[ntl][1] = v1; acc[ntl][2] = v2; acc[ntl][3] = v3;
        s1 += v0 + v1; q1 += v0 * v0 + v1 * v1;
        s2 += v2 + v3; q2 += v2 * v2 + v3 * v3;
    }
#pragma unroll
    for (int o = 1; o < 4; o <<= 1) {
        s1 += __shfl_xor_sync(0xffffffffu, s1, o); q1 += __shfl_xor_sync(0xffffffffu, q1, o);
        s2 += __shfl_xor_sync(0xffffffffu, s2, o); q2 += __shfl_xor_sync(0xffffffffu, q2, o);
    }
    float* sS = (float*)smc;
    float* sQ = (float*)smc + 256;
    if ((lane & 3) == 0) {
        sS[r1 * 2 + wn] = s1; sQ[r1 * 2 + wn] = q1;
        sS[r2 * 2 + wn] = s2; sQ[r2 * 2 + wn] = q2;
    }
    __syncthreads();
    float mu1 = (sS[r1 * 2] + sS[r1 * 2 + 1]) * (1.f / D_);
    float rs1 = rsqrtf((sQ[r1 * 2] + sQ[r1 * 2 + 1]) * (1.f / D_) - mu1 * mu1 + EPS);
    float mu2 = (sS[r2 * 2] + sS[r2 * 2 + 1]) * (1.f / D_);
    float rs2 = rsqrtf((sQ[r2 * 2] + sQ[r2 * 2 + 1]) * (1.f / D_) - mu2 * mu2 + EPS);
#pragma unroll
    for (int ntl = 0; ntl < 16; ntl++) {
        int cb = wn * 128 + ntl * 8 + 2 * (lane & 3);
        float2 gg = *(const float2*)(em_g + cb);
        float2 bt = *(const float2*)(em_beta + cb);
        float h0 = (acc[ntl][0] - mu1) * rs1 * gg.x + bt.x;
        float h1 = (acc[ntl][1] - mu1) * rs1 * gg.y + bt.y;
        float h2 = (acc[ntl][2] - mu2) * rs2 * gg.x + bt.x;
        float h3 = (acc[ntl][3] - mu2) * rs2 * gg.y + bt.y;
        *(uint32_t*)(g_h_bf + gm1 * D_ + cb) = pack_bf2(h0, h1);
        *(uint32_t*)(g_h_bf + gm2 * D_ + cb) = pack_bf2(h2, h3);
    }
}

// ---------------- kernel: A_t / B_t (HMMA) ----------------
__global__ __launch_bounds__(512) void k_t_pre_mma()
{
    extern __shared__ char smc[];
    const uint32_t sbase = s2u(smc);
    const int tid = threadIdx.x;
    const int lane = tid & 31, wid = tid >> 5;
    const int wm = wid & 7, wn = wid >> 3;
    const int m0 = blockIdx.x * 128;
    const int n0 = (blockIdx.y & 1) * 256;
    const int half = blockIdx.y >> 1;
    const int bcol0 = half * 256;

    float acc[16][4];
#pragma unroll
    for (int i = 0; i < 16; i++)
#pragma unroll
        for (int j = 0; j < 4; j++) acc[i][j] = 0.f;

    mma_pipeline(g_tlembs_bf, D_, KP1,
                 g_tmW_bf + (size_t)n0 * MD + bcol0, MD, 256 / 32, m0, sbase, acc);

    float* out = half ? g_Bt : g_At;
    const int r1 = wm * 16 + (lane >> 2);
    const int gm1 = m0 + r1, gm2 = gm1 + 8;
#pragma unroll
    for (int ntl = 0; ntl < 16; ntl++) {
        int cb = n0 + wn * 128 + ntl * 8 + 2 * (lane & 3);
        if (gm1 < KP1) *(float2*)(out + gm1 * MD + cb) = make_float2(acc[ntl][0], acc[ntl][1]);
        if (gm2 < KP1) *(float2*)(out + gm2 * MD + cb) = make_float2(acc[ntl][2], acc[ntl][3]);
    }
}

// ---------------- kernel: emission lse GEMM + query scatter ----------------
__global__ __launch_bounds__(512) void k_em_mma(const float* __restrict__ decb)
{
    extern __shared__ char smc[];
    const uint32_t sbase = s2u(smc);
    const int tid = threadIdx.x;
    const int lane = tid & 31, wid = tid >> 5;
    const int wm = wid & 7, wn = wid >> 3;
    const int m0 = blockIdx.x * 128;

    float acc[16][4];
#pragma unroll
    for (int i = 0; i < 16; i++)
#pragma unroll
        for (int j = 0; j < 4; j++) acc[i][j] = 0.f;

    mma_pipeline(g_decW_bf, D_, V_, g_h_bf, D_, D_ / 32, m0, sbase, acc);

    const int lr1 = wm * 16 + (lane >> 2);
    const int lr2 = lr1 + 8;
    const int gm1 = m0 + lr1, gm2 = m0 + lr2;
    const bool ok1 = gm1 < V_, ok2 = gm2 < V_;
    const float b1 = ok1 ? __ldg(&decb[gm1]) : 0.f;
    const float b2 = ok2 ? __ldg(&decb[gm2]) : 0.f;
    float* cps = (float*)smc;   // [256][8]
#pragma unroll
    for (int ntl = 0; ntl < 16; ntl++) {
        int c0 = wn * 128 + ntl * 8 + 2 * (lane & 3);
        float lg0 = acc[ntl][0] + b1, lg1 = acc[ntl][1] + b1;
        float lg2 = acc[ntl][2] + b2, lg3 = acc[ntl][3] + b2;
        *(float2*)(smc + EM_LOG + lr1 * 1040 + 4 * c0) = make_float2(lg0, lg1);
        *(float2*)(smc + EM_LOG + lr2 * 1040 + 4 * c0) = make_float2(lg2, lg3);
        float v0 = (ok1 ? __expf(lg0) : 0.f) + (ok2 ? __expf(lg2) : 0.f);
        float v1 = (ok1 ? __expf(lg1) : 0.f) + (ok2 ? __expf(lg3) : 0.f);
#pragma unroll
        for (int o = 4; o < 32; o <<= 1) {
            v0 += __shfl_xor_sync(0xffffffffu, v0, o);
            v1 += __shfl_xor_sync(0xffffffffu, v1, o);
        }
        if (lane < 4) {
            int cc = wn * 128 + ntl * 8 + 2 * lane;
            cps[cc * 8 + wm] = v0;
            cps[(cc + 1) * 8 + wm] = v1;
        }
    }
    __syncthreads();
    if (tid < 256) {
        float s = 0.f;
#pragma unroll
        for (int w = 0; w < 8; w++) s += cps[tid * 8 + w];
        g_part_em[blockIdx.x * K_ + tid] = s;
    }
    // query scatter: rows of this tile = vocab ids
    if (tid < 128) {
        int gm = m0 + tid;
        if (gm < V_) {
            int p0 = g_qoff_em[gm], p1 = g_qoff_em[gm + 1];
            const float* lrow = (const float*)(smc + EM_LOG + tid * 1040);
            for (int p = p0; p < p1; p++) {
                uint32_t pk = g_qdat_em[p];
                int qid = pk & 0x1FFFF;
                int zt = pk >> 17;
                g_q_em[qid] = lrow[zt];
            }
        }
    }
}

// ---------------- kernel: reduce emission partials ----------------
__global__ __launch_bounds__(128) void k_red_em()
{
    const int k = blockIdx.x;
    const int tid = threadIdx.x;
    __shared__ float red[128];
    float s = 0.f;
    for (int c = tid; c < NVT; c += 128) s += g_part_em[c * K_ + k];
    red[tid] = s;
    __syncthreads();
    for (int st = 64; st; st >>= 1) {
        if (tid < st) red[tid] += red[tid + st];
        __syncthreads();
    }
    if (tid == 0) g_lse_em[k] = __logf(red[0]);
}

// ---------------- kernel: fused th-build + transition GEMM + lse + query scatter ----------------
__global__ __launch_bounds__(512) void k_tr_fused(
    const float* __restrict__ tlembs, const float* __restrict__ tm_bias,
    const float* __restrict__ tn_g, const float* __restrict__ tn_beta,
    const float* __restrict__ tdb)
{
    extern __shared__ char smc[];
    const uint32_t sbase = s2u(smc);
    const int tid = threadIdx.x;
    const int lane = tid & 31, wid = tid >> 5;
    const int wm = wid & 7, wn = wid >> 3;
    const int m0 = blockIdx.x * 128;

    // preload B chunk 0 (tdW rows 0..255, cols 0..31)
    {
        int u = tid;
        int row = u >> 2, q = u & 3;
        cp16(sbase + TRF_B0 + row * 80 + q * 16, g_tdW_bf + (size_t)row * MD + q * 8, true);
        u = tid + 512; row = u >> 2; q = u & 3;
        cp16(sbase + TRF_B0 + row * 80 + q * 16, g_tdW_bf + (size_t)row * MD + q * 8, true);
        CP_COMMIT();
    }

    // ---- phase 1: build th tile (128 rows x 512 bf16) resident in smem ----
#pragma unroll 1
    for (int k8 = 0; k8 < 8; k8++) {
        int rr = wid * 8 + k8;
        int gm = m0 + rr;
        char* rbase = smc + rr * 1040;
        if (gm < R2) {
            int i = gm / KP1, j = gm - i * KP1;
            float v[16];
            float s = 0.f, q = 0.f;
#pragma unroll
            for (int qq = 0; qq < 4; qq++) {
                int e = 4 * lane + 128 * qq;
                float4 c4 = (qq < 2) ? *(const float4*)(tlembs + i * D_ + e)
                                     : *(const float4*)(tlembs + j * D_ + (e - 256));
                float4 a4 = *(const float4*)(g_At + i * MD + e);
                float4 b4 = *(const float4*)(g_Bt + j * MD + e);
                float4 bi = *(const float4*)(tm_bias + e);
                float v0 = c4.x + fmaxf(a4.x + b4.x + bi.x, 0.f);
                float v1 = c4.y + fmaxf(a4.y + b4.y + bi.y, 0.f);
                float v2 = c4.z + fmaxf(a4.z + b4.z + bi.z, 0.f);
                float v3 = c4.w + fmaxf(a4.w + b4.w + bi.w, 0.f);
                v[qq * 4 + 0] = v0; v[qq * 4 + 1] = v1; v[qq * 4 + 2] = v2; v[qq * 4 + 3] = v3;
                s += v0 + v1 + v2 + v3;
                q += v0 * v0 + v1 * v1 + v2 * v2 + v3 * v3;
            }
#pragma unroll
            for (int o = 16; o; o >>= 1) {
                s += __shfl_xor_sync(0xffffffffu, s, o);
                q += __shfl_xor_sync(0xffffffffu, q, o);
            }
            float mu = s * (1.f / MD);
            float rstd = rsqrtf(q * (1.f / MD) - mu * mu + EPS);
#pragma unroll
            for (int qq = 0; qq < 4; qq++) {
                int e = 4 * lane + 128 * qq;
                float4 gg = *(const float4*)(tn_g + e);
                float4 bt = *(const float4*)(tn_beta + e);
                float h0 = (v[qq * 4 + 0] - mu) * rstd * gg.x + bt.x;
                float h1 = (v[qq * 4 + 1] - mu) * rstd * gg.y + bt.y;
                float h2 = (v[qq * 4 + 2] - mu) * rstd * gg.z + bt.z;
                float h3 = (v[qq * 4 + 3] - mu) * rstd * gg.w + bt.w;
                uint2 u2; u2.x = pack_bf2(h0, h1); u2.y = pack_bf2(h2, h3);
                *(uint2*)(rbase + 8 * lane + 256 * qq) = u2;
            }
        } else {
#pragma unroll
            for (int qq = 0; qq < 4; qq++)
                *(uint2*)(rbase + 8 * lane + 256 * qq) = make_uint2(0, 0);
        }
    }
    __syncthreads();

    // ---- phase 2: MMA over 16 K-chunks, A resident, B double-buffered ----
    float acc[16][4];
#pragma unroll
    for (int i = 0; i < 16; i++)
#pragma unroll
        for (int j = 0; j < 4; j++) acc[i][j] = 0.f;

    const uint32_t afrag = sbase + (wm * 16 + (lane & 15)) * 1040 + (lane >> 4) * 16;
    const uint32_t bfragbase = (wn * 128 + (lane & 7)) * 80 + (lane >> 3) * 16;

#pragma unroll 1
    for (int c = 0; c < 16; c++) {
        if (c + 1 < 16) {
            const uint32_t bso = ((c + 1) & 1) ? TRF_B1 : TRF_B0;
            int u = tid, row = u >> 2, q = u & 3;
            cp16(sbase + bso + row * 80 + q * 16,
                 g_tdW_bf + (size_t)row * MD + (c + 1) * 32 + q * 8, true);
            u = tid + 512; row = u >> 2; q = u & 3;
            cp16(sbase + bso + row * 80 + q * 16,
                 g_tdW_bf + (size_t)row * MD + (c + 1) * 32 + q * 8, true);
            CP_COMMIT();
            CP_WAIT(1);
        } else {
            CP_WAIT(0);
        }
        __syncthreads();
        uint32_t a0[4], a1[4];
        LDSM4(a0, afrag + c * 64);
        LDSM4(a1, afrag + c * 64 + 32);
        const uint32_t bb = sbase + ((c & 1) ? TRF_B1 : TRF_B0) + bfragbase;
#pragma unroll
        for (int ntl = 0; ntl < 16; ntl++) {
            uint32_t bq[4];
            LDSM4(bq, bb + ntl * 640);
            MMA16816(acc[ntl], a0, bq[0], bq[1]);
            MMA16816(acc[ntl], a1, bq[2], bq[3]);
        }
        __syncthreads();
    }

    // ---- phase 3: epilogue — logits to smem (over A region), row lse, queries ----
    const int lr1 = wm * 16 + (lane >> 2);
    const int lr2 = lr1 + 8;
    float e1 = 0.f, e2 = 0.f;
    const int colb = wn * 128 + 2 * (lane & 3);
#pragma unroll
    for (int ntl = 0; ntl < 16; ntl++) {
        int cb = colb + ntl * 8;
        float t0 = __ldg(&tdb[cb]), t1 = __ldg(&tdb[cb + 1]);
        float lg0 = acc[ntl][0] + t0, lg1 = acc[ntl][1] + t1;
        float lg2 = acc[ntl][2] + t0, lg3 = acc[ntl][3] + t1;
        *(float2*)(smc + lr1 * 1040 + 4 * cb) = make_float2(lg0, lg1);
        *(float2*)(smc + lr2 * 1040 + 4 * cb) = make_float2(lg2, lg3);
        e1 += __expf(lg0) + __expf(lg1);
        e2 += __expf(lg2) + __expf(lg3);
    }
#pragma unroll
    for (int o = 1; o < 4; o <<= 1) {
        e1 += __shfl_xor_sync(0xffffffffu, e1, o);
        e2 += __shfl_xor_sync(0xffffffffu, e2, o);
    }
    float* rps = (float*)(smc + TRF_RPS);
    if ((lane & 3) == 0) {
        rps[lr1 * 2 + wn] = e1;
        rps[lr2 * 2 + wn] = e2;
    }
    __syncthreads();
    float* lse = (float*)(smc + TRF_LSE);
    if (tid < 128) lse[tid] = __logf(rps[tid * 2] + rps[tid * 2 + 1]);
    __syncthreads();
    if (tid < 128) {
        int gm = m0 + tid;
        if (gm < R2) {
            int p0 = g_qoff_tr[gm], p1 = g_qoff_tr[gm + 1];
            const float* lrow = (const float*)(smc + tid * 1040);
            float l = lse[tid];
            for (int p = p0; p < p1; p++) {
                uint32_t pk = g_qdat_tr[p];
                int qid = pk & 0x1FFFF;
                int zt = pk >> 17;
                g_q_tr[qid] = lrow[zt] - l;
            }
        }
    }
}

// ---------------- kernel: final reduce ----------------
__global__ __launch_bounds__(512) void k_final(const int* __restrict__ z,
                                               float* __restrict__ out)
{
    __shared__ float red[512];
    const int b = blockIdx.x;
    const int t = threadIdx.x;
    const int idx = t * B_ + b;
    int zt = z[idx];
    red[t] = g_q_em[idx] - g_lse_em[zt] + g_q_tr[idx];
    __syncthreads();
    for (int s = 256; s; s >>= 1) {
        if (t < s) red[t] += red[t + s];
        __syncthreads();
    }
    if (t == 0) out[b] = red[0];
}

// ---------------- launch ----------------
extern "C" void kernel_launch(void* const* d_in, const int* in_sizes, int n_in,
                              void* d_out, int out_size)
{
    (void)in_sizes; (void)n_in; (void)out_size;
    const int*   x       = (const int*)d_in[0];
    const int*   z       = (const int*)d_in[1];
    const float* lembs   = (const float*)d_in[2];
    const float* tlembs  = (const float*)d_in[3];
    const float* decW    = (const float*)d_in[4];
    const float* decb    = (const float*)d_in[5];
    const float* emW     = (const float*)d_in[6];
    const float* em_bias = (const float*)d_in[7];
    const float* em_g    = (const float*)d_in[8];
    const float* em_beta = (const float*)d_in[9];
    const float* tdW     = (const float*)d_in[10];
    const float* tdb     = (const float*)d_in[11];
    const float* tmW     = (const float*)d_in[12];
    const float* tm_bias = (const float*)d_in[13];
    const float* tn_g    = (const float*)d_in[14];
    const float* tn_beta = (const float*)d_in[15];
    float* out = (float*)d_out;

    cudaFuncSetAttribute(k_em_mlp_mma, cudaFuncAttributeMaxDynamicSharedMemorySize, SMEMSZ);
    cudaFuncSetAttribute(k_t_pre_mma, cudaFuncAttributeMaxDynamicSharedMemorySize, SMEMSZ);
    cudaFuncSetAttribute(k_em_mma, cudaFuncAttributeMaxDynamicSharedMemorySize, EM_SMEM);
    cudaFuncSetAttribute(k_tr_fused, cudaFuncAttributeMaxDynamicSharedMemorySize, TRF_SMEM);

    __nv_bfloat16 *p_lembs_bf, *p_emW_bf, *p_tlembs_bf, *p_tmW_bf, *p_tdW_bf, *p_decW_bf;
    cudaGetSymbolAddress((void**)&p_lembs_bf, g_lembs_bf);
    cudaGetSymbolAddress((void**)&p_emW_bf, g_emW_bf);
    cudaGetSymbolAddress((void**)&p_tlembs_bf, g_tlembs_bf);
    cudaGetSymbolAddress((void**)&p_tmW_bf, g_tmW_bf);
    cudaGetSymbolAddress((void**)&p_tdW_bf, g_tdW_bf);
    cudaGetSymbolAddress((void**)&p_decW_bf, g_decW_bf);

    // weight conversions
    k_cvt<<<(K_ * D_ / 4 + 255) / 256, 256>>>(lembs, p_lembs_bf, K_ * D_ / 4);
    k_cvt<<<(D_ * D_ / 4 + 255) / 256, 256>>>(emW, p_emW_bf, D_ * D_ / 4);
    k_cvt<<<(KP1 * D_ / 4 + 255) / 256, 256>>>(tlembs, p_tlembs_bf, KP1 * D_ / 4);
    k_cvt<<<(MD * MD / 4 + 255) / 256, 256>>>(tmW, p_tmW_bf, MD * MD / 4);
    k_cvt<<<(K_ * MD / 4 + 255) / 256, 256>>>(tdW, p_tdW_bf, K_ * MD / 4);
    k_cvt<<<(V_ * D_ / 4 + 255) / 256, 256>>>(decW, p_decW_bf, V_ * D_ / 4);

    // query index build
    k_qzero<<<256, 256>>>();
    k_qcount<<<NQ / 256, 256>>>(x, z);
    k_scan1<<<(R2 + 255) / 256, 256>>>(0, R2);
    k_scan2<<<1, 512>>>((R2 + 255) / 256);
    k_scan3<<<(R2 + 255) / 256, 256>>>(0, R2);
    k_scan1<<<(V_ + 255) / 256, 256>>>(1, V_);
    k_scan2<<<1, 512>>>((V_ + 255) / 256);
    k_scan3<<<(V_ + 255) / 256, 256>>>(1, V_);
    k_qfill<<<NQ / 256, 256>>>(x, z);

    // compute
    k_em_mlp_mma<<<K_ / 128, 512, SMEMSZ>>>(lembs, em_bias, em_g, em_beta);
    k_t_pre_mma<<<dim3(3, 4), 512, SMEMSZ>>>();
    k_em_mma<<<NVT, 512, EM_SMEM>>>(decb);
    k_red_em<<<K_, 128>>>();
    k_tr_fused<<<NRT, 512, TRF_SMEM>>>(tlembs, tm_bias, tn_g, tn_beta, tdb);
    k_final<<<B_, 512>>>(z, out);
}

// round 9
// speedup vs baseline: 1.6939x; 1.0019x over previous
#include <cuda_runtime.h>
#include <cuda_bf16.h>
#include <math.h>
#include <stdint.h>

// ---------------- problem constants ----------------
#define K_   256
#define KP1  257
#define D_   256
#define V_   50000
#define T_   512
#define B_   256
#define MD   512              // M*D
#define R2   66049            // KP1*KP1
#define EPS  1e-5f
#define NQ   (T_ * B_)        // 131072 queries

#define NRT  517              // ceil(R2/128)
#define NVT  391              // ceil(V/128)

// ---------------- scratch ----------------
__device__ __nv_bfloat16 g_h_bf[K_ * D_];
__device__ float g_lse_em[K_];
__device__ float g_part_em[NVT * K_];
__device__ float g_At[KP1 * MD];
__device__ float g_Bt[KP1 * MD];
// bf16 weights
__device__ __nv_bfloat16 g_lembs_bf[K_ * D_];
__device__ __nv_bfloat16 g_emW_bf[D_ * D_];
__device__ __nv_bfloat16 g_tlembs_bf[KP1 * D_];
__device__ __nv_bfloat16 g_tmW_bf[MD * MD];
__device__ __nv_bfloat16 g_tdW_bf[K_ * MD];
__device__ __nv_bfloat16 g_decW_bf[(size_t)V_ * D_];
// query machinery
__device__ int g_cnt_tr[R2];
__device__ int g_cur_tr[R2];
__device__ int g_qoff_tr[R2 + 1];
__device__ int g_cnt_em[V_];
__device__ int g_cur_em[V_];
__device__ int g_qoff_em[V_ + 1];
__device__ int g_bsum[512];
__device__ uint32_t g_qdat_tr[NQ];
__device__ uint32_t g_qdat_em[NQ];
__device__ float g_q_tr[NQ];
__device__ float g_q_em[NQ];

// ================= helpers =================
__device__ __forceinline__ uint32_t s2u(const void* p) {
    uint32_t a;
    asm("{ .reg .u64 t; cvta.to.shared.u64 t, %1; cvt.u32.u64 %0, t; }" : "=r"(a) : "l"(p));
    return a;
}
__device__ __forceinline__ uint32_t pack_bf2(float a, float b) {
    uint32_t u;
    asm("cvt.rn.bf16x2.f32 %0, %1, %2;" : "=r"(u) : "f"(b), "f"(a));
    return u;
}
__device__ __forceinline__ void cp16(uint32_t dst, const void* src, bool ok) {
    int sz = ok ? 16 : 0;
    asm volatile("cp.async.cg.shared.global [%0], [%1], 16, %2;"
                 :: "r"(dst), "l"(src), "r"(sz) : "memory");
}
#define CP_COMMIT() asm volatile("cp.async.commit_group;" ::: "memory")
#define CP_WAIT(n)  asm volatile("cp.async.wait_group %0;" :: "n"(n) : "memory")

#define LDSM4(r, addr) \
    asm volatile("ldmatrix.sync.aligned.m8n8.x4.shared.b16 {%0,%1,%2,%3}, [%4];" \
                 : "=r"((r)[0]), "=r"((r)[1]), "=r"((r)[2]), "=r"((r)[3]) : "r"(addr))

#define MMA16816(c, a, b0v, b1v) \
    asm volatile("mma.sync.aligned.m16n8k16.row.col.f32.bf16.bf16.f32 " \
                 "{%0,%1,%2,%3}, {%4,%5,%6,%7}, {%8,%9}, {%0,%1,%2,%3};" \
                 : "+f"((c)[0]), "+f"((c)[1]), "+f"((c)[2]), "+f"((c)[3]) \
                 : "r"((a)[0]), "r"((a)[1]), "r"((a)[2]), "r"((a)[3]), "r"(b0v), "r"(b1v))

// pipeline smem layout (em_mlp / t_pre / em_mma): A 128x80, B 256x80, 2 stages
#define ASZ    10240
#define STAGE  30720
#define SMEMSZ (2 * STAGE)
// em_mma: logits tile after stages
#define EM_LOG  61440
#define EM_SMEM (EM_LOG + 133120)
// tr_fused: resident A (th) tile 128 x 1040B; B stages; lse; rps
#define TRF_B0   133120
#define TRF_B1   153600
#define TRF_LSE  174080
#define TRF_RPS  174592
#define TRF_SMEM 175616

// ---------------- HMMA pipeline core (A+B staged) ----------------
__device__ __forceinline__ void mma_pipeline(
    const __nv_bfloat16* __restrict__ Aptr, int lda, int AM,
    const __nv_bfloat16* __restrict__ Bptr, int ldb,
    int NC, int m0, uint32_t sbase, float acc[16][4])
{
    const int tid = threadIdx.x;
    const int lane = tid & 31, wid = tid >> 5;
    const int wm = wid & 7, wn = wid >> 3;

    const int arow = tid >> 2, aq = tid & 3;
    const int gmA = m0 + arow;
    const bool aok = gmA < AM;
    const __nv_bfloat16* asrc = Aptr + (size_t)(aok ? gmA : 0) * lda + aq * 8;
    const __nv_bfloat16* bsrc1 = Bptr + (size_t)arow * ldb + aq * 8;
    const __nv_bfloat16* bsrc2 = Bptr + (size_t)(128 + arow) * ldb + aq * 8;
    const uint32_t adst  = sbase + arow * 80 + aq * 16;
    const uint32_t bdst1 = sbase + ASZ + arow * 80 + aq * 16;
    const uint32_t bdst2 = sbase + ASZ + (128 + arow) * 80 + aq * 16;

    const uint32_t afrag = sbase + (wm * 16 + (lane & 15)) * 80 + (lane >> 4) * 16;
    const uint32_t bfrag = sbase + ASZ + (wn * 128 + (lane & 7)) * 80 + (lane >> 3) * 16;

    cp16(adst, asrc, aok);
    cp16(bdst1, bsrc1, true);
    cp16(bdst2, bsrc2, true);
    CP_COMMIT();

#pragma unroll 1
    for (int c = 0; c < NC; c++) {
        if (c + 1 < NC) {
            const uint32_t nso = ((c + 1) & 1) * STAGE;
            const int koff = (c + 1) * 32;
            cp16(adst + nso, asrc + koff, aok);
            cp16(bdst1 + nso, bsrc1 + koff, true);
            cp16(bdst2 + nso, bsrc2 + koff, true);
            CP_COMMIT();
            CP_WAIT(1);
        } else {
            CP_WAIT(0);
        }
        __syncthreads();
        const uint32_t so = (c & 1) * STAGE;
        uint32_t a0[4], a1[4];
        LDSM4(a0, afrag + so);
        LDSM4(a1, afrag + so + 32);
        const uint32_t bb = bfrag + so;
#pragma unroll
        for (int ntl = 0; ntl < 16; ntl++) {
            uint32_t bq[4];
            LDSM4(bq, bb + ntl * 640);
            MMA16816(acc[ntl], a0, bq[0], bq[1]);
            MMA16816(acc[ntl], a1, bq[2], bq[3]);
        }
        __syncthreads();
    }
}

// ---------------- fp32 -> bf16 conversion ----------------
__global__ __launch_bounds__(256) void k_cvt(const float* __restrict__ src,
                                             __nv_bfloat16* __restrict__ dst, int nq)
{
    int i = blockIdx.x * 256 + threadIdx.x;
    if (i < nq) {
        float4 f = *(const float4*)(src + (size_t)i * 4);
        uint2 u; u.x = pack_bf2(f.x, f.y); u.y = pack_bf2(f.z, f.w);
        *(uint2*)(dst + (size_t)i * 4) = u;
    }
}

// ---------------- query index build ----------------
__global__ __launch_bounds__(256) void k_qzero()
{
    int i = blockIdx.x * 256 + threadIdx.x;
    int stride = gridDim.x * 256;
    for (int k = i; k < R2; k += stride) { g_cnt_tr[k] = 0; g_cur_tr[k] = 0; }
    for (int k = i; k < V_; k += stride) { g_cnt_em[k] = 0; g_cur_em[k] = 0; }
}

__global__ __launch_bounds__(256) void k_qcount(const int* __restrict__ x,
                                                const int* __restrict__ z)
{
    int idx = blockIdx.x * 256 + threadIdx.x;
    int t = idx >> 8;
    int zp1 = (t >= 1) ? z[idx - B_] : K_;
    int zp2 = (t >= 2) ? z[idx - 2 * B_] : K_;
    atomicAdd(&g_cnt_tr[zp2 * KP1 + zp1], 1);
    atomicAdd(&g_cnt_em[x[idx]], 1);
}

__global__ __launch_bounds__(256) void k_scan1(int which, int n)
{
    const int* cnt = which ? g_cnt_em : g_cnt_tr;
    __shared__ int sh[256];
    int i = blockIdx.x * 256 + threadIdx.x;
    sh[threadIdx.x] = (i < n) ? cnt[i] : 0;
    __syncthreads();
    for (int s = 128; s; s >>= 1) {
        if (threadIdx.x < s) sh[threadIdx.x] += sh[threadIdx.x + s];
        __syncthreads();
    }
    if (threadIdx.x == 0) g_bsum[blockIdx.x] = sh[0];
}

__global__ __launch_bounds__(512) void k_scan2(int nb)
{
    __shared__ int sh[512];
    int v = (threadIdx.x < nb) ? g_bsum[threadIdx.x] : 0;
    sh[threadIdx.x] = v;
    __syncthreads();
    for (int o = 1; o < 512; o <<= 1) {
        int t = (threadIdx.x >= o) ? sh[threadIdx.x - o] : 0;
        __syncthreads();
        sh[threadIdx.x] += t;
        __syncthreads();
    }
    if (threadIdx.x < nb) g_bsum[threadIdx.x] = sh[threadIdx.x] - v;  // exclusive
}

__global__ __launch_bounds__(256) void k_scan3(int which, int n)
{
    const int* cnt = which ? g_cnt_em : g_cnt_tr;
    int* qoff = which ? g_qoff_em : g_qoff_tr;
    __shared__ int sh[256];
    int i = blockIdx.x * 256 + threadIdx.x;
    int v = (i < n) ? cnt[i] : 0;
    sh[threadIdx.x] = v;
    __syncthreads();
    for (int o = 1; o < 256; o <<= 1) {
        int t = (threadIdx.x >= o) ? sh[threadIdx.x - o] : 0;
        __syncthreads();
        sh[threadIdx.x] += t;
        __syncthreads();
    }
    int incl = sh[threadIdx.x];
    int base = g_bsum[blockIdx.x];
    if (i < n) qoff[i] = base + incl - v;
    if (i == n - 1) qoff[n] = base + incl;
}

__global__ __launch_bounds__(256) void k_qfill(const int* __restrict__ x,
                                               const int* __restrict__ z)
{
    int idx = blockIdx.x * 256 + threadIdx.x;
    int t = idx >> 8;
    int zt = z[idx];
    int zp1 = (t >= 1) ? z[idx - B_] : K_;
    int zp2 = (t >= 2) ? z[idx - 2 * B_] : K_;
    int lin = zp2 * KP1 + zp1;
    uint32_t pk = (uint32_t)idx | ((uint32_t)zt << 17);
    int pos = g_qoff_tr[lin] + atomicAdd(&g_cur_tr[lin], 1);
    g_qdat_tr[pos] = pk;
    int xt = x[idx];
    pos = g_qoff_em[xt] + atomicAdd(&g_cur_em[xt], 1);
    g_qdat_em[pos] = pk;
}

// ---------------- kernel: emission MLP (HMMA) -> g_h_bf ----------------
__global__ __launch_bounds__(512) void k_em_mlp_mma(
    const float* __restrict__ lembs, const float* __restrict__ em_bias,
    const float* __restrict__ em_g, const float* __restrict__ em_beta)
{
    extern __shared__ char smc[];
    const uint32_t sbase = s2u(smc);
    const int tid = threadIdx.x;
    const int lane = tid & 31, wid = tid >> 5;
    const int wm = wid & 7, wn = wid >> 3;
    const int m0 = blockIdx.x * 128;

    float acc[16][4];
#pragma unroll
    for (int i = 0; i < 16; i++)
#pragma unroll
        for (int j = 0; j < 4; j++) acc[i][j] = 0.f;

    mma_pipeline(g_lembs_bf, D_, K_, g_emW_bf, D_, D_ / 32, m0, sbase, acc);

    const int r1 = wm * 16 + (lane >> 2);
    const int r2 = r1 + 8;
    const int gm1 = m0 + r1, gm2 = m0 + r2;
    float s1 = 0.f, q1 = 0.f, s2 = 0.f, q2 = 0.f;
#pragma unroll
    for (int ntl = 0; ntl < 16; ntl++) {
        int cb = wn * 128 + ntl * 8 + 2 * (lane & 3);
        float2 b2v = *(const float2*)(em_bias + cb);
        float2 l1 = *(const float2*)(lembs + gm1 * D_ + cb);
        float2 l2 = *(const float2*)(lembs + gm2 * D_ + cb);
        float v0 = l1.x + fmaxf(acc[ntl][0] + b2v.x, 0.f);
        float v1 = l1.y + fmaxf(acc[ntl][1] + b2v.y, 0.f);
        float v2 = l2.x + fmaxf(acc[ntl][2] + b2v.x, 0.f);
        float v3 = l2.y + fmaxf(acc[ntl][3] + b2v.y, 0.f);
        acc[ntl][0] = v0; acc[ntl][1] = v1; acc[ntl][2] = v2; acc[ntl][3] = v3;
        s1 += v0 + v1; q1 += v0 * v0 + v1 * v1;
        s2 += v2 + v3; q2 += v2 * v2 + v3 * v3;
    }
#pragma unroll
    for (int o = 1; o < 4; o <<= 1) {
        s1 += __shfl_xor_sync(0xffffffffu, s1, o); q1 += __shfl_xor_sync(0xffffffffu, q1, o);
        s2 += __shfl_xor_sync(0xffffffffu, s2, o); q2 += __shfl_xor_sync(0xffffffffu, q2, o);
    }
    float* sS = (float*)smc;
    float* sQ = (float*)smc + 256;
    if ((lane & 3) == 0) {
        sS[r1 * 2 + wn] = s1; sQ[r1 * 2 + wn] = q1;
        sS[r2 * 2 + wn] = s2; sQ[r2 * 2 + wn] = q2;
    }
    __syncthreads();
    float mu1 = (sS[r1 * 2] + sS[r1 * 2 + 1]) * (1.f / D_);
    float rs1 = rsqrtf((sQ[r1 * 2] + sQ[r1 * 2 + 1]) * (1.f / D_) - mu1 * mu1 + EPS);
    float mu2 = (sS[r2 * 2] + sS[r2 * 2 + 1]) * (1.f / D_);
    float rs2 = rsqrtf((sQ[r2 * 2] + sQ[r2 * 2 + 1]) * (1.f / D_) - mu2 * mu2 + EPS);
#pragma unroll
    for (int ntl = 0; ntl < 16; ntl++) {
        int cb = wn * 128 + ntl * 8 + 2 * (lane & 3);
        float2 gg = *(const float2*)(em_g + cb);
        float2 bt = *(const float2*)(em_beta + cb);
        float h0 = (acc[ntl][0] - mu1) * rs1 * gg.x + bt.x;
        float h1 = (acc[ntl][1] - mu1) * rs1 * gg.y + bt.y;
        float h2 = (acc[ntl][2] - mu2) * rs2 * gg.x + bt.x;
        float h3 = (acc[ntl][3] - mu2) * rs2 * gg.y + bt.y;
        *(uint32_t*)(g_h_bf + gm1 * D_ + cb) = pack_bf2(h0, h1);
        *(uint32_t*)(g_h_bf + gm2 * D_ + cb) = pack_bf2(h2, h3);
    }
}

// ---------------- kernel: A_t / B_t (HMMA) ----------------
__global__ __launch_bounds__(512) void k_t_pre_mma()
{
    extern __shared__ char smc[];
    const uint32_t sbase = s2u(smc);
    const int tid = threadIdx.x;
    const int lane = tid & 31, wid = tid >> 5;
    const int wm = wid & 7, wn = wid >> 3;
    const int m0 = blockIdx.x * 128;
    const int n0 = (blockIdx.y & 1) * 256;
    const int half = blockIdx.y >> 1;
    const int bcol0 = half * 256;

    float acc[16][4];
#pragma unroll
    for (int i = 0; i < 16; i++)
#pragma unroll
        for (int j = 0; j < 4; j++) acc[i][j] = 0.f;

    mma_pipeline(g_tlembs_bf, D_, KP1,
                 g_tmW_bf + (size_t)n0 * MD + bcol0, MD, 256 / 32, m0, sbase, acc);

    float* out = half ? g_Bt : g_At;
    const int r1 = wm * 16 + (lane >> 2);
    const int gm1 = m0 + r1, gm2 = gm1 + 8;
#pragma unroll
    for (int ntl = 0; ntl < 16; ntl++) {
        int cb = n0 + wn * 128 + ntl * 8 + 2 * (lane & 3);
        if (gm1 < KP1) *(float2*)(out + gm1 * MD + cb) = make_float2(acc[ntl][0], acc[ntl][1]);
        if (gm2 < KP1) *(float2*)(out + gm2 * MD + cb) = make_float2(acc[ntl][2], acc[ntl][3]);
    }
}

// ---------------- kernel: emission lse GEMM + query scatter ----------------
__global__ __launch_bounds__(512) void k_em_mma(const float* __restrict__ decb)
{
    extern __shared__ char smc[];
    const uint32_t sbase = s2u(smc);
    const int tid = threadIdx.x;
    const int lane = tid & 31, wid = tid >> 5;
    const int wm = wid & 7, wn = wid >> 3;
    const int m0 = blockIdx.x * 128;

    float acc[16][4];
#pragma unroll
    for (int i = 0; i < 16; i++)
#pragma unroll
        for (int j = 0; j < 4; j++) acc[i][j] = 0.f;

    mma_pipeline(g_decW_bf, D_, V_, g_h_bf, D_, D_ / 32, m0, sbase, acc);

    const int lr1 = wm * 16 + (lane >> 2);
    const int lr2 = lr1 + 8;
    const int gm1 = m0 + lr1, gm2 = m0 + lr2;
    const bool ok1 = gm1 < V_, ok2 = gm2 < V_;
    const float b1 = ok1 ? __ldg(&decb[gm1]) : 0.f;
    const float b2 = ok2 ? __ldg(&decb[gm2]) : 0.f;
    float* cps = (float*)smc;   // [256][8]
#pragma unroll
    for (int ntl = 0; ntl < 16; ntl++) {
        int c0 = wn * 128 + ntl * 8 + 2 * (lane & 3);
        float lg0 = acc[ntl][0] + b1, lg1 = acc[ntl][1] + b1;
        float lg2 = acc[ntl][2] + b2, lg3 = acc[ntl][3] + b2;
        *(float2*)(smc + EM_LOG + lr1 * 1040 + 4 * c0) = make_float2(lg0, lg1);
        *(float2*)(smc + EM_LOG + lr2 * 1040 + 4 * c0) = make_float2(lg2, lg3);
        float v0 = (ok1 ? __expf(lg0) : 0.f) + (ok2 ? __expf(lg2) : 0.f);
        float v1 = (ok1 ? __expf(lg1) : 0.f) + (ok2 ? __expf(lg3) : 0.f);
#pragma unroll
        for (int o = 4; o < 32; o <<= 1) {
            v0 += __shfl_xor_sync(0xffffffffu, v0, o);
            v1 += __shfl_xor_sync(0xffffffffu, v1, o);
        }
        if (lane < 4) {
            int cc = wn * 128 + ntl * 8 + 2 * lane;
            cps[cc * 8 + wm] = v0;
            cps[(cc + 1) * 8 + wm] = v1;
        }
    }
    __syncthreads();
    if (tid < 256) {
        float s = 0.f;
#pragma unroll
        for (int w = 0; w < 8; w++) s += cps[tid * 8 + w];
        g_part_em[blockIdx.x * K_ + tid] = s;
    }
    // query scatter: rows of this tile = vocab ids
    if (tid < 128) {
        int gm = m0 + tid;
        if (gm < V_) {
            int p0 = g_qoff_em[gm], p1 = g_qoff_em[gm + 1];
            const float* lrow = (const float*)(smc + EM_LOG + tid * 1040);
            for (int p = p0; p < p1; p++) {
                uint32_t pk = g_qdat_em[p];
                int qid = pk & 0x1FFFF;
                int zt = pk >> 17;
                g_q_em[qid] = lrow[zt];
            }
        }
    }
}

// ---------------- kernel: reduce emission partials ----------------
__global__ __launch_bounds__(128) void k_red_em()
{
    const int k = blockIdx.x;
    const int tid = threadIdx.x;
    __shared__ float red[128];
    float s = 0.f;
    for (int c = tid; c < NVT; c += 128) s += g_part_em[c * K_ + k];
    red[tid] = s;
    __syncthreads();
    for (int st = 64; st; st >>= 1) {
        if (tid < st) red[tid] += red[tid + st];
        __syncthreads();
    }
    if (tid == 0) g_lse_em[k] = __logf(red[0]);
}

// ---------------- kernel: fused th-build + transition GEMM + lse + query scatter ----------------
__global__ __launch_bounds__(512) void k_tr_fused(
    const float* __restrict__ tlembs, const float* __restrict__ tm_bias,
    const float* __restrict__ tn_g, const float* __restrict__ tn_beta,
    const float* __restrict__ tdb)
{
    extern __shared__ char smc[];
    const uint32_t sbase = s2u(smc);
    const int tid = threadIdx.x;
    const int lane = tid & 31, wid = tid >> 5;
    const int wm = wid & 7, wn = wid >> 3;
    const int m0 = blockIdx.x * 128;

    // preload B chunk 0 (tdW rows 0..255, cols 0..31)
    {
        int u = tid;
        int row = u >> 2, q = u & 3;
        cp16(sbase + TRF_B0 + row * 80 + q * 16, g_tdW_bf + (size_t)row * MD + q * 8, true);
        u = tid + 512; row = u >> 2; q = u & 3;
        cp16(sbase + TRF_B0 + row * 80 + q * 16, g_tdW_bf + (size_t)row * MD + q * 8, true);
        CP_COMMIT();
    }

    // ---- phase 1: build th tile (128 rows x 512 bf16) resident in smem ----
#pragma unroll 1
    for (int k8 = 0; k8 < 8; k8++) {
        int rr = wid * 8 + k8;
        int gm = m0 + rr;
        char* rbase = smc + rr * 1040;
        if (gm < R2) {
            int i = gm / KP1, j = gm - i * KP1;
            float v[16];
            float s = 0.f, q = 0.f;
#pragma unroll
            for (int qq = 0; qq < 4; qq++) {
                int e = 4 * lane + 128 * qq;
                float4 c4 = (qq < 2) ? *(const float4*)(tlembs + i * D_ + e)
                                     : *(const float4*)(tlembs + j * D_ + (e - 256));
                float4 a4 = *(const float4*)(g_At + i * MD + e);
                float4 b4 = *(const float4*)(g_Bt + j * MD + e);
                float4 bi = *(const float4*)(tm_bias + e);
                float v0 = c4.x + fmaxf(a4.x + b4.x + bi.x, 0.f);
                float v1 = c4.y + fmaxf(a4.y + b4.y + bi.y, 0.f);
                float v2 = c4.z + fmaxf(a4.z + b4.z + bi.z, 0.f);
                float v3 = c4.w + fmaxf(a4.w + b4.w + bi.w, 0.f);
                v[qq * 4 + 0] = v0; v[qq * 4 + 1] = v1; v[qq * 4 + 2] = v2; v[qq * 4 + 3] = v3;
                s += v0 + v1 + v2 + v3;
                q += v0 * v0 + v1 * v1 + v2 * v2 + v3 * v3;
            }
#pragma unroll
            for (int o = 16; o; o >>= 1) {
                s += __shfl_xor_sync(0xffffffffu, s, o);
                q += __shfl_xor_sync(0xffffffffu, q, o);
            }
            float mu = s * (1.f / MD);
            float rstd = rsqrtf(q * (1.f / MD) - mu * mu + EPS);
#pragma unroll
            for (int qq = 0; qq < 4; qq++) {
                int e = 4 * lane + 128 * qq;
                float4 gg = *(const float4*)(tn_g + e);
                float4 bt = *(const float4*)(tn_beta + e);
                float h0 = (v[qq * 4 + 0] - mu) * rstd * gg.x + bt.x;
                float h1 = (v[qq * 4 + 1] - mu) * rstd * gg.y + bt.y;
                float h2 = (v[qq * 4 + 2] - mu) * rstd * gg.z + bt.z;
                float h3 = (v[qq * 4 + 3] - mu) * rstd * gg.w + bt.w;
                uint2 u2; u2.x = pack_bf2(h0, h1); u2.y = pack_bf2(h2, h3);
                *(uint2*)(rbase + 8 * lane + 256 * qq) = u2;
            }
        } else {
#pragma unroll
            for (int qq = 0; qq < 4; qq++)
                *(uint2*)(rbase + 8 * lane + 256 * qq) = make_uint2(0, 0);
        }
    }
    __syncthreads();

    // ---- phase 2: MMA over 16 K-chunks, A resident, B double-buffered ----
    float acc[16][4];
#pragma unroll
    for (int i = 0; i < 16; i++)
#pragma unroll
        for (int j = 0; j < 4; j++) acc[i][j] = 0.f;

    const uint32_t afrag = sbase + (wm * 16 + (lane & 15)) * 1040 + (lane >> 4) * 16;
    const uint32_t bfragbase = (wn * 128 + (lane & 7)) * 80 + (lane >> 3) * 16;

#pragma unroll 1
    for (int c = 0; c < 16; c++) {
        if (c + 1 < 16) {
            const uint32_t bso = ((c + 1) & 1) ? TRF_B1 : TRF_B0;
            int u = tid, row = u >> 2, q = u & 3;
            cp16(sbase + bso + row * 80 + q * 16,
                 g_tdW_bf + (size_t)row * MD + (c + 1) * 32 + q * 8, true);
            u = tid + 512; row = u >> 2; q = u & 3;
            cp16(sbase + bso + row * 80 + q * 16,
                 g_tdW_bf + (size_t)row * MD + (c + 1) * 32 + q * 8, true);
            CP_COMMIT();
            CP_WAIT(1);
        } else {
            CP_WAIT(0);
        }
        __syncthreads();
        uint32_t a0[4], a1[4];
        LDSM4(a0, afrag + c * 64);
        LDSM4(a1, afrag + c * 64 + 32);
        const uint32_t bb = sbase + ((c & 1) ? TRF_B1 : TRF_B0) + bfragbase;
#pragma unroll
        for (int ntl = 0; ntl < 16; ntl++) {
            uint32_t bq[4];
            LDSM4(bq, bb + ntl * 640);
            MMA16816(acc[ntl], a0, bq[0], bq[1]);
            MMA16816(acc[ntl], a1, bq[2], bq[3]);
        }
        __syncthreads();
    }

    // ---- phase 3: epilogue — logits to smem (over A region), row lse, queries ----
    const int lr1 = wm * 16 + (lane >> 2);
    const int lr2 = lr1 + 8;
    float e1 = 0.f, e2 = 0.f;
    const int colb = wn * 128 + 2 * (lane & 3);
#pragma unroll
    for (int ntl = 0; ntl < 16; ntl++) {
        int cb = colb + ntl * 8;
        float t0 = __ldg(&tdb[cb]), t1 = __ldg(&tdb[cb + 1]);
        float lg0 = acc[ntl][0] + t0, lg1 = acc[ntl][1] + t1;
        float lg2 = acc[ntl][2] + t0, lg3 = acc[ntl][3] + t1;
        *(float2*)(smc + lr1 * 1040 + 4 * cb) = make_float2(lg0, lg1);
        *(float2*)(smc + lr2 * 1040 + 4 * cb) = make_float2(lg2, lg3);
        e1 += __expf(lg0) + __expf(lg1);
        e2 += __expf(lg2) + __expf(lg3);
    }
#pragma unroll
    for (int o = 1; o < 4; o <<= 1) {
        e1 += __shfl_xor_sync(0xffffffffu, e1, o);
        e2 += __shfl_xor_sync(0xffffffffu, e2, o);
    }
    float* rps = (float*)(smc + TRF_RPS);
    if ((lane & 3) == 0) {
        rps[lr1 * 2 + wn] = e1;
        rps[lr2 * 2 + wn] = e2;
    }
    __syncthreads();
    float* lse = (float*)(smc + TRF_LSE);
    if (tid < 128) lse[tid] = __logf(rps[tid * 2] + rps[tid * 2 + 1]);
    __syncthreads();
    if (tid < 128) {
        int gm = m0 + tid;
        if (gm < R2) {
            int p0 = g_qoff_tr[gm], p1 = g_qoff_tr[gm + 1];
            const float* lrow = (const float*)(smc + tid * 1040);
            float l = lse[tid];
            for (int p = p0; p < p1; p++) {
                uint32_t pk = g_qdat_tr[p];
                int qid = pk & 0x1FFFF;
                int zt = pk >> 17;
                g_q_tr[qid] = lrow[zt] - l;
            }
        }
    }
}

// ---------------- kernel: final reduce ----------------
__global__ __launch_bounds__(512) void k_final(const int* __restrict__ z,
                                               float* __restrict__ out)
{
    __shared__ float red[512];
    const int b = blockIdx.x;
    const int t = threadIdx.x;
    const int idx = t * B_ + b;
    int zt = z[idx];
    red[t] = g_q_em[idx] - g_lse_em[zt] + g_q_tr[idx];
    __syncthreads();
    for (int s = 256; s; s >>= 1) {
        if (t < s) red[t] += red[t + s];
        __syncthreads();
    }
    if (t == 0) out[b] = red[0];
}

// ---------------- launch ----------------
extern "C" void kernel_launch(void* const* d_in, const int* in_sizes, int n_in,
                              void* d_out, int out_size)
{
    (void)in_sizes; (void)n_in; (void)out_size;
    const int*   x       = (const int*)d_in[0];
    const int*   z       = (const int*)d_in[1];
    const float* lembs   = (const float*)d_in[2];
    const float* tlembs  = (const float*)d_in[3];
    const float* decW    = (const float*)d_in[4];
    const float* decb    = (const float*)d_in[5];
    const float* emW     = (const float*)d_in[6];
    const float* em_bias = (const float*)d_in[7];
    const float* em_g    = (const float*)d_in[8];
    const float* em_beta = (const float*)d_in[9];
    const float* tdW     = (const float*)d_in[10];
    const float* tdb     = (const float*)d_in[11];
    const float* tmW     = (const float*)d_in[12];
    const float* tm_bias = (const float*)d_in[13];
    const float* tn_g    = (const float*)d_in[14];
    const float* tn_beta = (const float*)d_in[15];
    float* out = (float*)d_out;

    cudaFuncSetAttribute(k_em_mlp_mma, cudaFuncAttributeMaxDynamicSharedMemorySize, SMEMSZ);
    cudaFuncSetAttribute(k_t_pre_mma, cudaFuncAttributeMaxDynamicSharedMemorySize, SMEMSZ);
    cudaFuncSetAttribute(k_em_mma, cudaFuncAttributeMaxDynamicSharedMemorySize, EM_SMEM);
    cudaFuncSetAttribute(k_tr_fused, cudaFuncAttributeMaxDynamicSharedMemorySize, TRF_SMEM);

    __nv_bfloat16 *p_lembs_bf, *p_emW_bf, *p_tlembs_bf, *p_tmW_bf, *p_tdW_bf, *p_decW_bf;
    cudaGetSymbolAddress((void**)&p_lembs_bf, g_lembs_bf);
    cudaGetSymbolAddress((void**)&p_emW_bf, g_emW_bf);
    cudaGetSymbolAddress((void**)&p_tlembs_bf, g_tlembs_bf);
    cudaGetSymbolAddress((void**)&p_tmW_bf, g_tmW_bf);
    cudaGetSymbolAddress((void**)&p_tdW_bf, g_tdW_bf);
    cudaGetSymbolAddress((void**)&p_decW_bf, g_decW_bf);

    // weight conversions
    k_cvt<<<(K_ * D_ / 4 + 255) / 256, 256>>>(lembs, p_lembs_bf, K_ * D_ / 4);
    k_cvt<<<(D_ * D_ / 4 + 255) / 256, 256>>>(emW, p_emW_bf, D_ * D_ / 4);
    k_cvt<<<(KP1 * D_ / 4 + 255) / 256, 256>>>(tlembs, p_tlembs_bf, KP1 * D_ / 4);
    k_cvt<<<(MD * MD / 4 + 255) / 256, 256>>>(tmW, p_tmW_bf, MD * MD / 4);
    k_cvt<<<(K_ * MD / 4 + 255) / 256, 256>>>(tdW, p_tdW_bf, K_ * MD / 4);
    k_cvt<<<(V_ * D_ / 4 + 255) / 256, 256>>>(decW, p_decW_bf, V_ * D_ / 4);

    // query index build
    k_qzero<<<256, 256>>>();
    k_qcount<<<NQ / 256, 256>>>(x, z);
    k_scan1<<<(R2 + 255) / 256, 256>>>(0, R2);
    k_scan2<<<1, 512>>>((R2 + 255) / 256);
    k_scan3<<<(R2 + 255) / 256, 256>>>(0, R2);
    k_scan1<<<(V_ + 255) / 256, 256>>>(1, V_);
    k_scan2<<<1, 512>>>((V_ + 255) / 256);
    k_scan3<<<(V_ + 255) / 256, 256>>>(1, V_);
    k_qfill<<<NQ / 256, 256>>>(x, z);

    // compute
    k_em_mlp_mma<<<K_ / 128, 512, SMEMSZ>>>(lembs, em_bias, em_g, em_beta);
    k_t_pre_mma<<<dim3(3, 4), 512, SMEMSZ>>>();
    k_em_mma<<<NVT, 512, EM_SMEM>>>(decb);
    k_red_em<<<K_, 128>>>();
    k_tr_fused<<<NRT, 512, TRF_SMEM>>>(tlembs, tm_bias, tn_g, tn_beta, tdb);
    k_final<<<B_, 512>>>(z, out);
}